// round 7
// baseline (speedup 1.0000x reference)
#include <cuda_runtime.h>
#include <math.h>

#define LQ 1024
#define PK 4096
#define DM 512
#define NH 8
#define DH 64
#define NR 50
#define TPB 128            // p-tile for bias_exp_v2
#define SPLIT 8            // split-K factor for attnv
#define CHUNK (PK / SPLIT) // 512

// ---------------- scratch (device globals; no allocations allowed) ----------
__device__ float g_Qp[LQ * DM];            // 2 MB
__device__ float g_Kp[PK * DM];            // 8 MB
__device__ float g_Vp[PK * DM];            // 8 MB
__device__ float g_S[NH * LQ * PK];        // 134 MB  logits -> exp(logits), [H][L][P]
__device__ float g_rZ[LQ * NH];            // 1/Z per (l,h)
__device__ float g_O[LQ * DM];             // attention output (pre out-proj)
__device__ float g_Op[SPLIT * LQ * DM];    // 16 MB   split-K partials
__device__ float g_Xo[LQ * DM];            // out-proj result

// ---------------------------------------------------------------------------
// Generic NT SGEMM: C = alpha * A @ B^T (+ bias)
// ---------------------------------------------------------------------------
__global__ __launch_bounds__(256) void sgemm_nt(
    const float* __restrict__ A, int lda, int aStride,
    const float* __restrict__ B, int ldb, int bStride,
    float* __restrict__ C, int ldc, long cStride,
    int K, float alpha, const float* __restrict__ bias)
{
    __shared__ float As[8][132];
    __shared__ float Bs[8][132];

    const int bz = blockIdx.z;
    const float* Ab = A + (long)bz * aStride;
    const float* Bb = B + (long)bz * bStride;
    float* Cb = C + (long)bz * cStride;

    const int m0 = blockIdx.y * 128;
    const int n0 = blockIdx.x * 128;
    const int t  = threadIdx.x;
    const int tx = t & 15;
    const int ty = t >> 4;
    const int lrow = t >> 1;
    const int lk   = (t & 1) * 4;

    float acc[8][8];
#pragma unroll
    for (int i = 0; i < 8; i++)
#pragma unroll
        for (int j = 0; j < 8; j++) acc[i][j] = 0.0f;

    const float* aPtr = Ab + (long)(m0 + lrow) * lda + lk;
    const float* bPtr = Bb + (long)(n0 + lrow) * ldb + lk;

    for (int k0 = 0; k0 < K; k0 += 8) {
        float4 av = *(const float4*)(aPtr + k0);
        float4 bv = *(const float4*)(bPtr + k0);
        As[lk + 0][lrow] = av.x; As[lk + 1][lrow] = av.y;
        As[lk + 2][lrow] = av.z; As[lk + 3][lrow] = av.w;
        Bs[lk + 0][lrow] = bv.x; Bs[lk + 1][lrow] = bv.y;
        Bs[lk + 2][lrow] = bv.z; Bs[lk + 3][lrow] = bv.w;
        __syncthreads();

#pragma unroll
        for (int kk = 0; kk < 8; kk++) {
            float4 a0 = *(const float4*)&As[kk][ty * 8];
            float4 a1 = *(const float4*)&As[kk][ty * 8 + 4];
            float4 b0 = *(const float4*)&Bs[kk][tx * 8];
            float4 b1 = *(const float4*)&Bs[kk][tx * 8 + 4];
            float ar[8] = {a0.x, a0.y, a0.z, a0.w, a1.x, a1.y, a1.z, a1.w};
            float br_[8] = {b0.x, b0.y, b0.z, b0.w, b1.x, b1.y, b1.z, b1.w};
#pragma unroll
            for (int i = 0; i < 8; i++)
#pragma unroll
                for (int j = 0; j < 8; j++)
                    acc[i][j] = fmaf(ar[i], br_[j], acc[i][j]);
        }
        __syncthreads();
    }

    float bb[8];
#pragma unroll
    for (int j = 0; j < 8; j++) bb[j] = bias ? bias[n0 + tx * 8 + j] : 0.0f;

#pragma unroll
    for (int i = 0; i < 8; i++) {
        float* crow = Cb + (long)(m0 + ty * 8 + i) * ldc + n0 + tx * 8;
        float4 o0 = make_float4(fmaf(alpha, acc[i][0], bb[0]),
                                fmaf(alpha, acc[i][1], bb[1]),
                                fmaf(alpha, acc[i][2], bb[2]),
                                fmaf(alpha, acc[i][3], bb[3]));
        float4 o1 = make_float4(fmaf(alpha, acc[i][4], bb[4]),
                                fmaf(alpha, acc[i][5], bb[5]),
                                fmaf(alpha, acc[i][6], bb[6]),
                                fmaf(alpha, acc[i][7], bb[7]));
        *(float4*)crow       = o0;
        *(float4*)(crow + 4) = o1;
    }
}

// ---------------------------------------------------------------------------
// bias_exp_v2: one block per l. Double-buffered 128-p rbf tiles (dynamic smem),
// one barrier per tile. Warp w owns p-range [w*16, w*16+16); each row is
// handled by a lane PAIR (half=lane&1 takes r in [half*25, half*25+25)) ->
// smem address = 25*lane + r -> conflict-free. rbf read from smem exactly once.
// Wr held padded [h][half][32] so the weight operand is broadcast LDS.128.
// After shfl-combine, lane parity picks 4 heads -> all 32 lanes do S RW.
// ---------------------------------------------------------------------------
extern __shared__ float db_buf[];  // 2 * TPB * NR floats = 51.2 KB

__global__ __launch_bounds__(256) void bias_exp_v2(
    const float* __restrict__ rbf, const float* __restrict__ Wr,
    const float* __restrict__ br, float* __restrict__ S,
    float* __restrict__ rZ)
{
    __shared__ float wr_s[16 * 32];   // [h*2+half][32], zero-padded
    __shared__ float br_s[NH];
    __shared__ float zpart[8][NH];

    const int l    = blockIdx.x;
    const int t    = threadIdx.x;
    const int w    = t >> 5;
    const int lane = t & 31;
    const int row  = lane >> 1;
    const int half = lane & 1;

    for (int i = t; i < 16 * 32; i += 256) wr_s[i] = 0.0f;
    __syncthreads();
    for (int i = t; i < NH * NR; i += 256) {
        int h = i / NR, rr = i % NR;
        wr_s[(h * 2 + rr / 25) * 32 + (rr % 25)] = Wr[i];
    }
    if (t < NH) br_s[t] = br[t];

    const float* rbf_l = rbf + (long)l * PK * NR;
    float* buf0 = db_buf;
    float* buf1 = db_buf + TPB * NR;

    // prologue: tile 0
    {
        const float4* src = (const float4*)rbf_l;
        float4* dst = (float4*)buf0;
#pragma unroll 4
        for (int i = t; i < TPB * NR / 4; i += 256) dst[i] = src[i];
    }
    __syncthreads();   // also orders wr_s/br_s fills before first use

    float zacc[4] = {0.f, 0.f, 0.f, 0.f};
    const long lp = (long)l * PK;
    const int NT = PK / TPB;  // 32

    for (int tile = 0; tile < NT; tile++) {
        float* cur = (tile & 1) ? buf1 : buf0;
        float* nxt = (tile & 1) ? buf0 : buf1;

        if (tile + 1 < NT) {
            const float4* src = (const float4*)(rbf_l + (long)(tile + 1) * TPB * NR);
            float4* dst = (float4*)nxt;
#pragma unroll 4
            for (int i = t; i < TPB * NR / 4; i += 256) dst[i] = src[i];
        }

        // load 25 rbf values (this lane's half-row) into registers
        const float* rrow = cur + (w * 16 + row) * NR + half * 25;
        float rv[28];
#pragma unroll
        for (int r = 0; r < 25; r++) rv[r] = rrow[r];
        rv[25] = rv[26] = rv[27] = 0.0f;

        // 8 partial head dots over this half-row (vectorized weight loads)
        float acc[8];
#pragma unroll
        for (int h = 0; h < 8; h++) {
            const float4* wp = (const float4*)&wr_s[(h * 2 + half) * 32];
            float a0 = 0.f, a1 = 0.f, a2 = 0.f, a3 = 0.f;
#pragma unroll
            for (int q = 0; q < 7; q++) {
                float4 wv = wp[q];
                a0 = fmaf(rv[q * 4 + 0], wv.x, a0);
                a1 = fmaf(rv[q * 4 + 1], wv.y, a1);
                a2 = fmaf(rv[q * 4 + 2], wv.z, a2);
                a3 = fmaf(rv[q * 4 + 3], wv.w, a3);
            }
            acc[h] = (a0 + a1) + (a2 + a3);
        }

        // combine half-rows within the lane pair
#pragma unroll
        for (int h = 0; h < 8; h++)
            acc[h] += __shfl_xor_sync(0xFFFFFFFFu, acc[h], 1);

        // S read-modify-write: lane parity selects 4 heads; 16 same-parity
        // lanes cover 16 consecutive p -> 64B segments per head.
        const int p = tile * TPB + w * 16 + row;
#pragma unroll
        for (int j = 0; j < 4; j++) {
            const int h = half * 4 + j;
            float av = half ? acc[4 + j] : acc[j];
            float* ptr = S + (long)h * ((long)LQ * PK) + lp + p;
            float e = __expf(*ptr + av + br_s[h]);
            *ptr = e;
            zacc[j] += e;
        }

        __syncthreads();  // next-tile prefetch done AND cur free for overwrite
    }

    // reduce Z over same-parity lanes (covers all 16 rows of this warp)
#pragma unroll
    for (int j = 0; j < 4; j++) {
#pragma unroll
        for (int o = 2; o <= 16; o <<= 1)
            zacc[j] += __shfl_xor_sync(0xFFFFFFFFu, zacc[j], o);
    }
    if (lane < 2) {
#pragma unroll
        for (int j = 0; j < 4; j++) zpart[w][lane * 4 + j] = zacc[j];
    }
    __syncthreads();
    if (t < NH) {
        float s = 0.f;
#pragma unroll
        for (int ww = 0; ww < 8; ww++) s += zpart[ww][t];
        rZ[l * NH + t] = 1.0f / s;
    }
}

// ---------------------------------------------------------------------------
// attnv split-K: blockIdx.z = split s handles P-chunk [s*CHUNK, (s+1)*CHUNK).
// Unnormalized partials -> g_Op[s]. 128(l) x 64(d) tile, BK=16, 8x4 microtile.
// ---------------------------------------------------------------------------
__global__ __launch_bounds__(256) void attnv_split(
    const float* __restrict__ E, const float* __restrict__ V,
    float* __restrict__ Opart)
{
    __shared__ float As[16][132];
    __shared__ float Bs[16][64];

    const int h  = blockIdx.y;
    const int m0 = blockIdx.x * 128;
    const int sp = blockIdx.z;
    const float* Eh = E + (long)h * ((long)LQ * PK);

    const int t  = threadIdx.x;
    const int tx = t & 15;
    const int ty = t >> 4;
    const int arow = t >> 1;
    const int ak   = (t & 1) * 8;
    const int bk   = t >> 4;
    const int bf   = t & 15;

    float acc[8][4];
#pragma unroll
    for (int i = 0; i < 8; i++)
#pragma unroll
        for (int j = 0; j < 4; j++) acc[i][j] = 0.0f;

    const float* aPtr = Eh + (long)(m0 + arow) * PK + sp * CHUNK + ak;
    const float* bPtr = V + (long)(sp * CHUNK + bk) * DM + h * DH + bf * 4;

    for (int k0 = 0; k0 < CHUNK; k0 += 16) {
        float4 a0 = *(const float4*)(aPtr + k0);
        float4 a1 = *(const float4*)(aPtr + k0 + 4);
        float4 bv = *(const float4*)(bPtr + (long)k0 * DM);
        As[ak + 0][arow] = a0.x; As[ak + 1][arow] = a0.y;
        As[ak + 2][arow] = a0.z; As[ak + 3][arow] = a0.w;
        As[ak + 4][arow] = a1.x; As[ak + 5][arow] = a1.y;
        As[ak + 6][arow] = a1.z; As[ak + 7][arow] = a1.w;
        *(float4*)&Bs[bk][bf * 4] = bv;
        __syncthreads();

#pragma unroll
        for (int kk = 0; kk < 16; kk++) {
            float4 a0v = *(const float4*)&As[kk][ty * 8];
            float4 a1v = *(const float4*)&As[kk][ty * 8 + 4];
            float4 b   = *(const float4*)&Bs[kk][tx * 4];
            float ar[8] = {a0v.x, a0v.y, a0v.z, a0v.w, a1v.x, a1v.y, a1v.z, a1v.w};
            float br_[4] = {b.x, b.y, b.z, b.w};
#pragma unroll
            for (int i = 0; i < 8; i++)
#pragma unroll
                for (int j = 0; j < 4; j++)
                    acc[i][j] = fmaf(ar[i], br_[j], acc[i][j]);
        }
        __syncthreads();
    }

    float* Ob = Opart + (long)sp * ((long)LQ * DM);
#pragma unroll
    for (int i = 0; i < 8; i++) {
        int m = m0 + ty * 8 + i;
        float4 o = make_float4(acc[i][0], acc[i][1], acc[i][2], acc[i][3]);
        *(float4*)(Ob + (long)m * DM + h * DH + tx * 4) = o;
    }
}

// ---------------------------------------------------------------------------
// reduce split-K partials + apply 1/Z: O[l,d] = rZ[l, d/DH] * sum_s Op[s][l,d]
// ---------------------------------------------------------------------------
__global__ __launch_bounds__(256) void attnv_reduce(
    const float* __restrict__ Opart, const float* __restrict__ rZ,
    float* __restrict__ O)
{
    const int idx = blockIdx.x * 256 + threadIdx.x;  // float4 index
    const int l  = idx / (DM / 4);
    const int d4 = idx % (DM / 4);
    const int h  = d4 / (DH / 4);

    float4 s = make_float4(0.f, 0.f, 0.f, 0.f);
#pragma unroll
    for (int sp = 0; sp < SPLIT; sp++) {
        float4 v = *(const float4*)(Opart + (long)sp * ((long)LQ * DM) + (long)idx * 4);
        s.x += v.x; s.y += v.y; s.z += v.z; s.w += v.w;
    }
    const float sc = rZ[l * NH + h];
    s.x *= sc; s.y *= sc; s.z *= sc; s.w *= sc;
    *(float4*)(O + (long)idx * 4) = s;
}

// ---------------------------------------------------------------------------
// attn_mean[l,p] = (1/8) * sum_h E[h][l][p] * rZ[l,h]
// ---------------------------------------------------------------------------
__global__ __launch_bounds__(256) void attn_mean_kernel(
    const float* __restrict__ E, const float* __restrict__ rZ,
    float* __restrict__ out)
{
    __shared__ float rz[NH];
    const int l = blockIdx.x >> 4;
    const int p = ((blockIdx.x & 15) << 8) + threadIdx.x;
    if (threadIdx.x < NH) rz[threadIdx.x] = rZ[l * NH + threadIdx.x];
    __syncthreads();

    const float* El = E + (long)l * PK + p;
    float s = 0.0f;
#pragma unroll
    for (int h = 0; h < NH; h++)
        s = fmaf(El[(long)h * ((long)LQ * PK)], rz[h], s);
    out[(long)l * PK + p] = s * 0.125f;
}

// ---------------------------------------------------------------------------
// LayerNorm(query + Xo) * gamma + beta
// ---------------------------------------------------------------------------
__global__ __launch_bounds__(256) void ln_kernel(
    const float* __restrict__ query, const float* __restrict__ Xo,
    const float* __restrict__ gamma, const float* __restrict__ beta,
    float* __restrict__ y)
{
    __shared__ float rs[8], rq[8];
    const int l = blockIdx.x;
    const int t = threadIdx.x;
    const int lane = t & 31, warp = t >> 5;

    float2 q  = *(const float2*)(query + (long)l * DM + t * 2);
    float2 xo = *(const float2*)(Xo    + (long)l * DM + t * 2);
    float x0 = q.x + xo.x;
    float x1 = q.y + xo.y;

    float s  = x0 + x1;
    float sq = x0 * x0 + x1 * x1;
#pragma unroll
    for (int o = 16; o > 0; o >>= 1) {
        s  += __shfl_xor_sync(0xFFFFFFFFu, s, o);
        sq += __shfl_xor_sync(0xFFFFFFFFu, sq, o);
    }
    if (lane == 0) { rs[warp] = s; rq[warp] = sq; }
    __syncthreads();
    if (warp == 0) {
        float a = (lane < 8) ? rs[lane] : 0.0f;
        float b = (lane < 8) ? rq[lane] : 0.0f;
#pragma unroll
        for (int o = 4; o > 0; o >>= 1) {
            a += __shfl_xor_sync(0xFFFFFFFFu, a, o);
            b += __shfl_xor_sync(0xFFFFFFFFu, b, o);
        }
        if (lane == 0) { rs[0] = a; rq[0] = b; }
    }
    __syncthreads();

    const float mean = rs[0] * (1.0f / DM);
    const float var  = rq[0] * (1.0f / DM) - mean * mean;
    const float rstd = rsqrtf(var + 1e-5f);

    float2 g = *(const float2*)(gamma + t * 2);
    float2 b = *(const float2*)(beta + t * 2);
    float2 o;
    o.x = (x0 - mean) * rstd * g.x + b.x;
    o.y = (x1 - mean) * rstd * g.y + b.y;
    *(float2*)(y + (long)l * DM + t * 2) = o;
}

// ---------------------------------------------------------------------------
extern "C" void kernel_launch(void* const* d_in, const int* in_sizes, int n_in,
                              void* d_out, int out_size)
{
    const float* query = (const float*)d_in[0];
    const float* key   = (const float*)d_in[1];
    const float* value = (const float*)d_in[2];
    const float* rbf   = (const float*)d_in[3];
    const float* Wq = (const float*)d_in[4];
    const float* bq = (const float*)d_in[5];
    const float* Wk = (const float*)d_in[6];
    const float* bk = (const float*)d_in[7];
    const float* Wv = (const float*)d_in[8];
    const float* bv = (const float*)d_in[9];
    const float* Wr = (const float*)d_in[10];
    const float* br = (const float*)d_in[11];
    const float* Wo = (const float*)d_in[12];
    const float* bo = (const float*)d_in[13];
    const float* gamma = (const float*)d_in[14];
    const float* beta  = (const float*)d_in[15];
    float* out = (float*)d_out;

    float *Qp, *Kp, *Vp, *S, *rZ, *O, *Op, *Xo;
    cudaGetSymbolAddress((void**)&Qp, g_Qp);
    cudaGetSymbolAddress((void**)&Kp, g_Kp);
    cudaGetSymbolAddress((void**)&Vp, g_Vp);
    cudaGetSymbolAddress((void**)&S,  g_S);
    cudaGetSymbolAddress((void**)&rZ, g_rZ);
    cudaGetSymbolAddress((void**)&O,  g_O);
    cudaGetSymbolAddress((void**)&Op, g_Op);
    cudaGetSymbolAddress((void**)&Xo, g_Xo);

    const int dynsmem = 2 * TPB * NR * sizeof(float);  // 51.2 KB
    cudaFuncSetAttribute(bias_exp_v2, cudaFuncAttributeMaxDynamicSharedMemorySize,
                         dynsmem);

    // Projections: X @ W^T + b  (NT gemm, K=512)
    sgemm_nt<<<dim3(DM / 128, LQ / 128, 1), 256>>>(query, DM, 0, Wq, DM, 0,
                                                   Qp, DM, 0, DM, 1.0f, bq);
    sgemm_nt<<<dim3(DM / 128, PK / 128, 1), 256>>>(key, DM, 0, Wk, DM, 0,
                                                   Kp, DM, 0, DM, 1.0f, bk);
    sgemm_nt<<<dim3(DM / 128, PK / 128, 1), 256>>>(value, DM, 0, Wv, DM, 0,
                                                   Vp, DM, 0, DM, 1.0f, bv);

    // Scores: per head, S[h][l][p] = 0.125 * Q_h[l,:] . K_h[p,:]
    sgemm_nt<<<dim3(PK / 128, LQ / 128, NH), 256>>>(Qp, DM, DH, Kp, DM, DH,
                                                    S, PK, (long)LQ * PK,
                                                    DH, 0.125f, nullptr);

    // bias from cross_rbf + exp + per-(l,h) denominator
    bias_exp_v2<<<LQ, 256, dynsmem>>>(rbf, Wr, br, S, rZ);

    // attn @ V, split-K, then reduce + 1/Z
    attnv_split<<<dim3(LQ / 128, NH, SPLIT), 256>>>(S, Vp, Op);
    attnv_reduce<<<(LQ * DM / 4) / 256, 256>>>(Op, rZ, O);

    // attn.mean over heads -> second output
    attn_mean_kernel<<<LQ * (PK / 256), 256>>>(S, rZ, out + (long)LQ * DM);

    // output projection
    sgemm_nt<<<dim3(DM / 128, LQ / 128, 1), 256>>>(O, DM, 0, Wo, DM, 0,
                                                   Xo, DM, 0, DM, 1.0f, bo);

    // residual + layernorm -> first output
    ln_kernel<<<LQ, 256>>>(query, Xo, gamma, beta, out);
}

// round 10
// speedup vs baseline: 1.1304x; 1.1304x over previous
#include <cuda_runtime.h>
#include <cstdint>
#include <math.h>

#define LQ 1024
#define PK 4096
#define DM 512
#define NH 8
#define DH 64
#define NR 50
#define TPB 128            // p-tile for bias_exp_v3
#define PSPLIT 4           // p-chunk split for bias_exp_v3
#define PCH (PK / PSPLIT)  // 1024
#define SPLIT 8            // split-K factor for attnv
#define CHUNK (PK / SPLIT) // 512

// ---------------- scratch (device globals; no allocations allowed) ----------
__device__ float g_Qp[LQ * DM];            // 2 MB
__device__ float g_Kp[PK * DM];            // 8 MB
__device__ float g_Vp[PK * DM];            // 8 MB
__device__ float g_S[NH * LQ * PK];        // 134 MB  logits -> exp(logits), [H][L][P]
__device__ float g_Zp[PSPLIT * LQ * NH];   // Z partials per p-chunk
__device__ float g_rZ[LQ * NH];            // 1/Z per (l,h)
__device__ float g_O[LQ * DM];             // attention output (pre out-proj)
__device__ float g_Op[SPLIT * LQ * DM];    // 16 MB   split-K partials
__device__ float g_Xo[LQ * DM];            // out-proj result

// ---------------- cp.async helpers ----------------
__device__ __forceinline__ void cp16(void* smem_dst, const void* gmem_src) {
    unsigned s = (unsigned)__cvta_generic_to_shared(smem_dst);
    asm volatile("cp.async.cg.shared.global [%0], [%1], 16;" :: "r"(s), "l"(gmem_src));
}
__device__ __forceinline__ void cp_commit() {
    asm volatile("cp.async.commit_group;" ::: "memory");
}
__device__ __forceinline__ void cp_wait_all() {
    asm volatile("cp.async.wait_group 0;" ::: "memory");
}

// ---------------------------------------------------------------------------
// Generic NT SGEMM: C = alpha * A @ B^T (+ bias)
// ---------------------------------------------------------------------------
__global__ __launch_bounds__(256) void sgemm_nt(
    const float* __restrict__ A, int lda, int aStride,
    const float* __restrict__ B, int ldb, int bStride,
    float* __restrict__ C, int ldc, long cStride,
    int K, float alpha, const float* __restrict__ bias)
{
    __shared__ float As[8][132];
    __shared__ float Bs[8][132];

    const int bz = blockIdx.z;
    const float* Ab = A + (long)bz * aStride;
    const float* Bb = B + (long)bz * bStride;
    float* Cb = C + (long)bz * cStride;

    const int m0 = blockIdx.y * 128;
    const int n0 = blockIdx.x * 128;
    const int t  = threadIdx.x;
    const int tx = t & 15;
    const int ty = t >> 4;
    const int lrow = t >> 1;
    const int lk   = (t & 1) * 4;

    float acc[8][8];
#pragma unroll
    for (int i = 0; i < 8; i++)
#pragma unroll
        for (int j = 0; j < 8; j++) acc[i][j] = 0.0f;

    const float* aPtr = Ab + (long)(m0 + lrow) * lda + lk;
    const float* bPtr = Bb + (long)(n0 + lrow) * ldb + lk;

    for (int k0 = 0; k0 < K; k0 += 8) {
        float4 av = *(const float4*)(aPtr + k0);
        float4 bv = *(const float4*)(bPtr + k0);
        As[lk + 0][lrow] = av.x; As[lk + 1][lrow] = av.y;
        As[lk + 2][lrow] = av.z; As[lk + 3][lrow] = av.w;
        Bs[lk + 0][lrow] = bv.x; Bs[lk + 1][lrow] = bv.y;
        Bs[lk + 2][lrow] = bv.z; Bs[lk + 3][lrow] = bv.w;
        __syncthreads();

#pragma unroll
        for (int kk = 0; kk < 8; kk++) {
            float4 a0 = *(const float4*)&As[kk][ty * 8];
            float4 a1 = *(const float4*)&As[kk][ty * 8 + 4];
            float4 b0 = *(const float4*)&Bs[kk][tx * 8];
            float4 b1 = *(const float4*)&Bs[kk][tx * 8 + 4];
            float ar[8] = {a0.x, a0.y, a0.z, a0.w, a1.x, a1.y, a1.z, a1.w};
            float br_[8] = {b0.x, b0.y, b0.z, b0.w, b1.x, b1.y, b1.z, b1.w};
#pragma unroll
            for (int i = 0; i < 8; i++)
#pragma unroll
                for (int j = 0; j < 8; j++)
                    acc[i][j] = fmaf(ar[i], br_[j], acc[i][j]);
        }
        __syncthreads();
    }

    float bb[8];
#pragma unroll
    for (int j = 0; j < 8; j++) bb[j] = bias ? bias[n0 + tx * 8 + j] : 0.0f;

#pragma unroll
    for (int i = 0; i < 8; i++) {
        float* crow = Cb + (long)(m0 + ty * 8 + i) * ldc + n0 + tx * 8;
        float4 o0 = make_float4(fmaf(alpha, acc[i][0], bb[0]),
                                fmaf(alpha, acc[i][1], bb[1]),
                                fmaf(alpha, acc[i][2], bb[2]),
                                fmaf(alpha, acc[i][3], bb[3]));
        float4 o1 = make_float4(fmaf(alpha, acc[i][4], bb[4]),
                                fmaf(alpha, acc[i][5], bb[5]),
                                fmaf(alpha, acc[i][6], bb[6]),
                                fmaf(alpha, acc[i][7], bb[7]));
        *(float4*)crow       = o0;
        *(float4*)(crow + 4) = o1;
    }
}

// ---------------------------------------------------------------------------
// bias_exp_v3: grid (LQ, PSPLIT). Block (l, pc) handles p-chunk
// [pc*PCH, (pc+1)*PCH) = 8 tiles of 128 p. cp.async double-buffered prefetch
// (no LDG->STS stall), ONE barrier per tile. Warp w owns p-range
// [w*16, w*16+16) of the tile; lane pair per row (half = lane&1 covers
// r in [half*25, half*25+25)). Z partials -> g_Zp[pc], finalized later.
// ---------------------------------------------------------------------------
extern __shared__ float db_buf[];  // 2 * TPB * NR floats = 51.2 KB

__global__ __launch_bounds__(256) void bias_exp_v3(
    const float* __restrict__ rbf, const float* __restrict__ Wr,
    const float* __restrict__ br, float* __restrict__ S,
    float* __restrict__ Zp)
{
    __shared__ float wr_s[16 * 32];   // [h*2+half][32], zero-padded
    __shared__ float br_s[NH];
    __shared__ float zpart[8][NH];

    const int l    = blockIdx.x;
    const int pc   = blockIdx.y;
    const int t    = threadIdx.x;
    const int w    = t >> 5;
    const int lane = t & 31;
    const int row  = lane >> 1;
    const int half = lane & 1;

    for (int i = t; i < 16 * 32; i += 256) wr_s[i] = 0.0f;
    __syncthreads();
    for (int i = t; i < NH * NR; i += 256) {
        int h = i / NR, rr = i % NR;
        wr_s[(h * 2 + rr / 25) * 32 + (rr % 25)] = Wr[i];
    }
    if (t < NH) br_s[t] = br[t];

    const float* rbf_base = rbf + (long)l * PK * NR + (long)pc * PCH * NR;
    float* buf0 = db_buf;
    float* buf1 = db_buf + TPB * NR;
    const int NOPS = TPB * NR / 4;  // 1600 16B ops per tile

    // prologue: async-prefetch tile 0
    for (int i = t; i < NOPS; i += 256)
        cp16(buf0 + i * 4, rbf_base + (long)i * 4);
    cp_commit();

    float zacc[4] = {0.f, 0.f, 0.f, 0.f};
    const long lp = (long)l * PK;
    const int NT = PCH / TPB;  // 8

    for (int tile = 0; tile < NT; tile++) {
        float* cur = (tile & 1) ? buf1 : buf0;
        float* nxt = (tile & 1) ? buf0 : buf1;

        cp_wait_all();
        __syncthreads();  // cur complete for all threads; nxt free (readers done)

        if (tile + 1 < NT) {
            const float* src = rbf_base + (long)(tile + 1) * TPB * NR;
            for (int i = t; i < NOPS; i += 256)
                cp16(nxt + i * 4, src + (long)i * 4);
            cp_commit();
        }

        // load 25 rbf values (this lane's half-row) into registers
        const float* rrow = cur + (w * 16 + row) * NR + half * 25;
        float rv[28];
#pragma unroll
        for (int r = 0; r < 25; r++) rv[r] = rrow[r];
        rv[25] = rv[26] = rv[27] = 0.0f;

        // 8 partial head dots over this half-row (vectorized weight loads)
        float acc[8];
#pragma unroll
        for (int h = 0; h < 8; h++) {
            const float4* wp = (const float4*)&wr_s[(h * 2 + half) * 32];
            float a0 = 0.f, a1 = 0.f, a2 = 0.f, a3 = 0.f;
#pragma unroll
            for (int q = 0; q < 7; q++) {
                float4 wv = wp[q];
                a0 = fmaf(rv[q * 4 + 0], wv.x, a0);
                a1 = fmaf(rv[q * 4 + 1], wv.y, a1);
                a2 = fmaf(rv[q * 4 + 2], wv.z, a2);
                a3 = fmaf(rv[q * 4 + 3], wv.w, a3);
            }
            acc[h] = (a0 + a1) + (a2 + a3);
        }

        // combine half-rows within the lane pair
#pragma unroll
        for (int h = 0; h < 8; h++)
            acc[h] += __shfl_xor_sync(0xFFFFFFFFu, acc[h], 1);

        // S read-modify-write: lane parity selects 4 heads
        const int p = pc * PCH + tile * TPB + w * 16 + row;
#pragma unroll
        for (int j = 0; j < 4; j++) {
            const int h = half * 4 + j;
            float av = half ? acc[4 + j] : acc[j];
            float* ptr = S + (long)h * ((long)LQ * PK) + lp + p;
            float e = __expf(*ptr + av + br_s[h]);
            *ptr = e;
            zacc[j] += e;
        }
        // no trailing barrier: next iteration's top barrier provides ordering
    }

    // reduce Z over same-parity lanes (covers all 16 rows of this warp)
#pragma unroll
    for (int j = 0; j < 4; j++) {
#pragma unroll
        for (int o = 2; o <= 16; o <<= 1)
            zacc[j] += __shfl_xor_sync(0xFFFFFFFFu, zacc[j], o);
    }
    if (lane < 2) {
#pragma unroll
        for (int j = 0; j < 4; j++) zpart[w][lane * 4 + j] = zacc[j];
    }
    __syncthreads();
    if (t < NH) {
        float s = 0.f;
#pragma unroll
        for (int ww = 0; ww < 8; ww++) s += zpart[ww][t];
        Zp[((long)pc * LQ + l) * NH + t] = s;
    }
}

// ---------------------------------------------------------------------------
// rZ[l,h] = 1 / sum_pc Zp[pc][l][h]
// ---------------------------------------------------------------------------
__global__ __launch_bounds__(256) void rz_finalize(
    const float* __restrict__ Zp, float* __restrict__ rZ)
{
    const int i = blockIdx.x * 256 + threadIdx.x;  // LQ*NH = 8192
    float s = 0.f;
#pragma unroll
    for (int c = 0; c < PSPLIT; c++) s += Zp[(long)c * LQ * NH + i];
    rZ[i] = 1.0f / s;
}

// ---------------------------------------------------------------------------
// attnv split-K over HEAD PAIRS: block (l-tile, hp, sp) computes a 128(l) x
// 128(d over heads 2hp,2hp+1) tile of unnormalized O-partials over P-chunk sp.
// 8x8 microtile (same FMA density as sgemm_nt). Thread's 8 output columns lie
// entirely within one head (tx<8 -> head 2hp, else 2hp+1), so it reads only
// that head's E-plane from smem (plane pointer selected once).
// ---------------------------------------------------------------------------
__global__ __launch_bounds__(256) void attnv_split2(
    const float* __restrict__ E, const float* __restrict__ V,
    float* __restrict__ Opart)
{
    __shared__ float As0[16][132];
    __shared__ float As1[16][132];
    __shared__ float Bs[16][132];

    const int hp = blockIdx.y;           // head pair 0..3
    const int m0 = blockIdx.x * 128;
    const int sp = blockIdx.z;
    const float* Eh0 = E + (long)(2 * hp)     * ((long)LQ * PK);
    const float* Eh1 = E + (long)(2 * hp + 1) * ((long)LQ * PK);

    const int t  = threadIdx.x;
    const int tx = t & 15;
    const int ty = t >> 4;
    const int arow = t >> 1;
    const int ak   = (t & 1) * 8;
    const int bk   = t >> 4;
    const int bf   = t & 15;

    float acc[8][8];
#pragma unroll
    for (int i = 0; i < 8; i++)
#pragma unroll
        for (int j = 0; j < 8; j++) acc[i][j] = 0.0f;

    const float* a0Ptr = Eh0 + (long)(m0 + arow) * PK + sp * CHUNK + ak;
    const float* a1Ptr = Eh1 + (long)(m0 + arow) * PK + sp * CHUNK + ak;
    const float* bPtr  = V + (long)(sp * CHUNK + bk) * DM + hp * 128 + bf * 8;

    // per-thread A plane: columns tx*8..tx*8+7 are head 2hp iff tx<8
    const float (*Asel)[132] = (tx < 8) ? As0 : As1;

    for (int k0 = 0; k0 < CHUNK; k0 += 16) {
        float4 p00 = *(const float4*)(a0Ptr + k0);
        float4 p01 = *(const float4*)(a0Ptr + k0 + 4);
        float4 p10 = *(const float4*)(a1Ptr + k0);
        float4 p11 = *(const float4*)(a1Ptr + k0 + 4);
        float4 bv0 = *(const float4*)(bPtr + (long)k0 * DM);
        float4 bv1 = *(const float4*)(bPtr + (long)k0 * DM + 4);
        As0[ak + 0][arow] = p00.x; As0[ak + 1][arow] = p00.y;
        As0[ak + 2][arow] = p00.z; As0[ak + 3][arow] = p00.w;
        As0[ak + 4][arow] = p01.x; As0[ak + 5][arow] = p01.y;
        As0[ak + 6][arow] = p01.z; As0[ak + 7][arow] = p01.w;
        As1[ak + 0][arow] = p10.x; As1[ak + 1][arow] = p10.y;
        As1[ak + 2][arow] = p10.z; As1[ak + 3][arow] = p10.w;
        As1[ak + 4][arow] = p11.x; As1[ak + 5][arow] = p11.y;
        As1[ak + 6][arow] = p11.z; As1[ak + 7][arow] = p11.w;
        *(float4*)&Bs[bk][bf * 8]     = bv0;
        *(float4*)&Bs[bk][bf * 8 + 4] = bv1;
        __syncthreads();

#pragma unroll
        for (int kk = 0; kk < 16; kk++) {
            float4 a0 = *(const float4*)&Asel[kk][ty * 8];
            float4 a1 = *(const float4*)&Asel[kk][ty * 8 + 4];
            float4 b0 = *(const float4*)&Bs[kk][tx * 8];
            float4 b1 = *(const float4*)&Bs[kk][tx * 8 + 4];
            float ar[8] = {a0.x, a0.y, a0.z, a0.w, a1.x, a1.y, a1.z, a1.w};
            float br_[8] = {b0.x, b0.y, b0.z, b0.w, b1.x, b1.y, b1.z, b1.w};
#pragma unroll
            for (int i = 0; i < 8; i++)
#pragma unroll
                for (int j = 0; j < 8; j++)
                    acc[i][j] = fmaf(ar[i], br_[j], acc[i][j]);
        }
        __syncthreads();
    }

    float* Ob = Opart + (long)sp * ((long)LQ * DM);
#pragma unroll
    for (int i = 0; i < 8; i++) {
        int m = m0 + ty * 8 + i;
        float* orow = Ob + (long)m * DM + hp * 128 + tx * 8;
        *(float4*)orow       = make_float4(acc[i][0], acc[i][1], acc[i][2], acc[i][3]);
        *(float4*)(orow + 4) = make_float4(acc[i][4], acc[i][5], acc[i][6], acc[i][7]);
    }
}

// ---------------------------------------------------------------------------
// reduce split-K partials + apply 1/Z: O[l,d] = rZ[l, d/DH] * sum_s Op[s][l,d]
// ---------------------------------------------------------------------------
__global__ __launch_bounds__(256) void attnv_reduce(
    const float* __restrict__ Opart, const float* __restrict__ rZ,
    float* __restrict__ O)
{
    const int idx = blockIdx.x * 256 + threadIdx.x;  // float4 index
    const int l  = idx / (DM / 4);
    const int d4 = idx % (DM / 4);
    const int h  = d4 / (DH / 4);

    float4 s = make_float4(0.f, 0.f, 0.f, 0.f);
#pragma unroll
    for (int sp = 0; sp < SPLIT; sp++) {
        float4 v = *(const float4*)(Opart + (long)sp * ((long)LQ * DM) + (long)idx * 4);
        s.x += v.x; s.y += v.y; s.z += v.z; s.w += v.w;
    }
    const float sc = rZ[l * NH + h];
    s.x *= sc; s.y *= sc; s.z *= sc; s.w *= sc;
    *(float4*)(O + (long)idx * 4) = s;
}

// ---------------------------------------------------------------------------
// attn_mean[l,p] = (1/8) * sum_h E[h][l][p] * rZ[l,h]
// ---------------------------------------------------------------------------
__global__ __launch_bounds__(256) void attn_mean_kernel(
    const float* __restrict__ E, const float* __restrict__ rZ,
    float* __restrict__ out)
{
    __shared__ float rz[NH];
    const int l = blockIdx.x >> 4;
    const int p = ((blockIdx.x & 15) << 8) + threadIdx.x;
    if (threadIdx.x < NH) rz[threadIdx.x] = rZ[l * NH + threadIdx.x];
    __syncthreads();

    const float* El = E + (long)l * PK + p;
    float s = 0.0f;
#pragma unroll
    for (int h = 0; h < NH; h++)
        s = fmaf(El[(long)h * ((long)LQ * PK)], rz[h], s);
    out[(long)l * PK + p] = s * 0.125f;
}

// ---------------------------------------------------------------------------
// LayerNorm(query + Xo) * gamma + beta
// ---------------------------------------------------------------------------
__global__ __launch_bounds__(256) void ln_kernel(
    const float* __restrict__ query, const float* __restrict__ Xo,
    const float* __restrict__ gamma, const float* __restrict__ beta,
    float* __restrict__ y)
{
    __shared__ float rs[8], rq[8];
    const int l = blockIdx.x;
    const int t = threadIdx.x;
    const int lane = t & 31, warp = t >> 5;

    float2 q  = *(const float2*)(query + (long)l * DM + t * 2);
    float2 xo = *(const float2*)(Xo    + (long)l * DM + t * 2);
    float x0 = q.x + xo.x;
    float x1 = q.y + xo.y;

    float s  = x0 + x1;
    float sq = x0 * x0 + x1 * x1;
#pragma unroll
    for (int o = 16; o > 0; o >>= 1) {
        s  += __shfl_xor_sync(0xFFFFFFFFu, s, o);
        sq += __shfl_xor_sync(0xFFFFFFFFu, sq, o);
    }
    if (lane == 0) { rs[warp] = s; rq[warp] = sq; }
    __syncthreads();
    if (warp == 0) {
        float a = (lane < 8) ? rs[lane] : 0.0f;
        float b = (lane < 8) ? rq[lane] : 0.0f;
#pragma unroll
        for (int o = 4; o > 0; o >>= 1) {
            a += __shfl_xor_sync(0xFFFFFFFFu, a, o);
            b += __shfl_xor_sync(0xFFFFFFFFu, b, o);
        }
        if (lane == 0) { rs[0] = a; rq[0] = b; }
    }
    __syncthreads();

    const float mean = rs[0] * (1.0f / DM);
    const float var  = rq[0] * (1.0f / DM) - mean * mean;
    const float rstd = rsqrtf(var + 1e-5f);

    float2 g = *(const float2*)(gamma + t * 2);
    float2 b = *(const float2*)(beta + t * 2);
    float2 o;
    o.x = (x0 - mean) * rstd * g.x + b.x;
    o.y = (x1 - mean) * rstd * g.y + b.y;
    *(float2*)(y + (long)l * DM + t * 2) = o;
}

// ---------------------------------------------------------------------------
extern "C" void kernel_launch(void* const* d_in, const int* in_sizes, int n_in,
                              void* d_out, int out_size)
{
    const float* query = (const float*)d_in[0];
    const float* key   = (const float*)d_in[1];
    const float* value = (const float*)d_in[2];
    const float* rbf   = (const float*)d_in[3];
    const float* Wq = (const float*)d_in[4];
    const float* bq = (const float*)d_in[5];
    const float* Wk = (const float*)d_in[6];
    const float* bk = (const float*)d_in[7];
    const float* Wv = (const float*)d_in[8];
    const float* bv = (const float*)d_in[9];
    const float* Wr = (const float*)d_in[10];
    const float* br = (const float*)d_in[11];
    const float* Wo = (const float*)d_in[12];
    const float* bo = (const float*)d_in[13];
    const float* gamma = (const float*)d_in[14];
    const float* beta  = (const float*)d_in[15];
    float* out = (float*)d_out;

    float *Qp, *Kp, *Vp, *S, *Zp, *rZ, *O, *Op, *Xo;
    cudaGetSymbolAddress((void**)&Qp, g_Qp);
    cudaGetSymbolAddress((void**)&Kp, g_Kp);
    cudaGetSymbolAddress((void**)&Vp, g_Vp);
    cudaGetSymbolAddress((void**)&S,  g_S);
    cudaGetSymbolAddress((void**)&Zp, g_Zp);
    cudaGetSymbolAddress((void**)&rZ, g_rZ);
    cudaGetSymbolAddress((void**)&O,  g_O);
    cudaGetSymbolAddress((void**)&Op, g_Op);
    cudaGetSymbolAddress((void**)&Xo, g_Xo);

    const int dynsmem = 2 * TPB * NR * sizeof(float);  // 51.2 KB
    cudaFuncSetAttribute(bias_exp_v3, cudaFuncAttributeMaxDynamicSharedMemorySize,
                         dynsmem);

    // Projections: X @ W^T + b  (NT gemm, K=512)
    sgemm_nt<<<dim3(DM / 128, LQ / 128, 1), 256>>>(query, DM, 0, Wq, DM, 0,
                                                   Qp, DM, 0, DM, 1.0f, bq);
    sgemm_nt<<<dim3(DM / 128, PK / 128, 1), 256>>>(key, DM, 0, Wk, DM, 0,
                                                   Kp, DM, 0, DM, 1.0f, bk);
    sgemm_nt<<<dim3(DM / 128, PK / 128, 1), 256>>>(value, DM, 0, Wv, DM, 0,
                                                   Vp, DM, 0, DM, 1.0f, bv);

    // Scores: per head, S[h][l][p] = 0.125 * Q_h[l,:] . K_h[p,:]
    sgemm_nt<<<dim3(PK / 128, LQ / 128, NH), 256>>>(Qp, DM, DH, Kp, DM, DH,
                                                    S, PK, (long)LQ * PK,
                                                    DH, 0.125f, nullptr);

    // bias from cross_rbf + exp + per-(l,h,chunk) Z partials
    bias_exp_v3<<<dim3(LQ, PSPLIT), 256, dynsmem>>>(rbf, Wr, br, S, Zp);
    rz_finalize<<<(LQ * NH) / 256, 256>>>(Zp, rZ);

    // attn @ V, split-K over head pairs, then reduce + 1/Z
    attnv_split2<<<dim3(LQ / 128, NH / 2, SPLIT), 256>>>(S, Vp, Op);
    attnv_reduce<<<(LQ * DM / 4) / 256, 256>>>(Op, rZ, O);

    // attn.mean over heads -> second output
    attn_mean_kernel<<<LQ * (PK / 256), 256>>>(S, rZ, out + (long)LQ * DM);

    // output projection
    sgemm_nt<<<dim3(DM / 128, LQ / 128, 1), 256>>>(O, DM, 0, Wo, DM, 0,
                                                   Xo, DM, 0, DM, 1.0f, bo);

    // residual + layernorm -> first output
    ln_kernel<<<LQ, 256>>>(query, Xo, gamma, beta, out);
}

// round 12
// speedup vs baseline: 1.5775x; 1.3955x over previous
#include <cuda_runtime.h>
#include <cstdint>
#include <math.h>

#define LQ 1024
#define PK 4096
#define DM 512
#define NH 8
#define DH 64
#define NR 50
#define TPB 128            // p-tile for bias_exp_v3
#define PSPLIT 4           // p-chunk split for bias_exp_v3
#define PCH (PK / PSPLIT)  // 1024
#define SPLIT 8            // split-K factor for attnv
#define CHUNK (PK / SPLIT) // 512

// ---------------- scratch (device globals; no allocations allowed) ----------
__device__ float g_Qp[LQ * DM];            // 2 MB
__device__ float g_Kp[PK * DM];            // 8 MB
__device__ float g_Vp[PK * DM];            // 8 MB
__device__ float g_S[NH * LQ * PK];        // 134 MB  logits -> exp(logits), [H][L][P]
__device__ float g_Zp[PSPLIT * LQ * NH];   // Z partials per p-chunk
__device__ float g_rZ[LQ * NH];            // 1/Z per (l,h)
__device__ float g_O[LQ * DM];             // attention output (pre out-proj)
__device__ float g_Op[SPLIT * LQ * DM];    // 16 MB   split-K partials
__device__ float g_Xo[LQ * DM];            // out-proj result

// ---------------- cp.async helpers ----------------
__device__ __forceinline__ void cp16(void* smem_dst, const void* gmem_src) {
    unsigned s = (unsigned)__cvta_generic_to_shared(smem_dst);
    asm volatile("cp.async.cg.shared.global [%0], [%1], 16;" :: "r"(s), "l"(gmem_src));
}
__device__ __forceinline__ void cp_commit() {
    asm volatile("cp.async.commit_group;" ::: "memory");
}
__device__ __forceinline__ void cp_wait_all() {
    asm volatile("cp.async.wait_group 0;" ::: "memory");
}

// ---------------- tf32 mma helpers ----------------
__device__ __forceinline__ unsigned f2tf(float x) {
    unsigned r;
    asm("cvt.rna.tf32.f32 %0, %1;" : "=r"(r) : "f"(x));
    return r;
}
__device__ __forceinline__ void mma_tf32(float* d, const unsigned* a,
                                         const unsigned* b) {
    asm volatile(
        "mma.sync.aligned.m16n8k8.row.col.f32.tf32.tf32.f32 "
        "{%0,%1,%2,%3}, {%4,%5,%6,%7}, {%8,%9}, {%0,%1,%2,%3};\n"
        : "+f"(d[0]), "+f"(d[1]), "+f"(d[2]), "+f"(d[3])
        : "r"(a[0]), "r"(a[1]), "r"(a[2]), "r"(a[3]),
          "r"(b[0]), "r"(b[1]));
}

// ---------------------------------------------------------------------------
// tf32 NT GEMM: C[m,n] = alpha * sum_k A[m*lda+k]*B[n*ldb+k] (+ bias[n]).
// 128x128 tile, BK=16, 256 threads (8 warps, 2x4 warp grid, 64x32 per warp).
// A,B staged to k-major smem as tf32 (RNA). M,N mult of 128, K mult of 16.
// ---------------------------------------------------------------------------
__global__ __launch_bounds__(256) void tgemm_nt(
    const float* __restrict__ A, int lda, int aStride,
    const float* __restrict__ B, int ldb, int bStride,
    float* __restrict__ C, int ldc, long cStride,
    int K, float alpha, const float* __restrict__ bias)
{
    __shared__ unsigned As[16][132];
    __shared__ unsigned Bs[16][132];

    const int bz = blockIdx.z;
    const float* Ab = A + (long)bz * aStride;
    const float* Bb = B + (long)bz * bStride;
    float* Cb = C + (long)bz * cStride;

    const int m0 = blockIdx.y * 128;
    const int n0 = blockIdx.x * 128;
    const int t    = threadIdx.x;
    const int w    = t >> 5;
    const int lane = t & 31;
    const int grp  = lane >> 2;
    const int tid4 = lane & 3;
    const int wm = (w & 1) * 64;
    const int wn = (w >> 1) * 32;

    const int srow = t >> 1;        // 0..127
    const int sk   = (t & 1) * 8;   // 0 or 8

    float acc[4][4][4];
#pragma unroll
    for (int mi = 0; mi < 4; mi++)
#pragma unroll
        for (int nj = 0; nj < 4; nj++)
#pragma unroll
            for (int q = 0; q < 4; q++) acc[mi][nj][q] = 0.0f;

    const float* aPtr = Ab + (long)(m0 + srow) * lda + sk;
    const float* bPtr = Bb + (long)(n0 + srow) * ldb + sk;

    for (int k0 = 0; k0 < K; k0 += 16) {
        float4 a0v = *(const float4*)(aPtr + k0);
        float4 a1v = *(const float4*)(aPtr + k0 + 4);
        float4 b0v = *(const float4*)(bPtr + k0);
        float4 b1v = *(const float4*)(bPtr + k0 + 4);
        As[sk + 0][srow] = f2tf(a0v.x); As[sk + 1][srow] = f2tf(a0v.y);
        As[sk + 2][srow] = f2tf(a0v.z); As[sk + 3][srow] = f2tf(a0v.w);
        As[sk + 4][srow] = f2tf(a1v.x); As[sk + 5][srow] = f2tf(a1v.y);
        As[sk + 6][srow] = f2tf(a1v.z); As[sk + 7][srow] = f2tf(a1v.w);
        Bs[sk + 0][srow] = f2tf(b0v.x); Bs[sk + 1][srow] = f2tf(b0v.y);
        Bs[sk + 2][srow] = f2tf(b0v.z); Bs[sk + 3][srow] = f2tf(b0v.w);
        Bs[sk + 4][srow] = f2tf(b1v.x); Bs[sk + 5][srow] = f2tf(b1v.y);
        Bs[sk + 6][srow] = f2tf(b1v.z); Bs[sk + 7][srow] = f2tf(b1v.w);
        __syncthreads();

#pragma unroll
        for (int ks = 0; ks < 16; ks += 8) {
            unsigned af[4][4];
#pragma unroll
            for (int mi = 0; mi < 4; mi++) {
                int mb = wm + mi * 16;
                af[mi][0] = As[ks + tid4][mb + grp];
                af[mi][1] = As[ks + tid4][mb + 8 + grp];
                af[mi][2] = As[ks + 4 + tid4][mb + grp];
                af[mi][3] = As[ks + 4 + tid4][mb + 8 + grp];
            }
#pragma unroll
            for (int nj = 0; nj < 4; nj++) {
                unsigned bf[2];
                bf[0] = Bs[ks + tid4][wn + nj * 8 + grp];
                bf[1] = Bs[ks + 4 + tid4][wn + nj * 8 + grp];
#pragma unroll
                for (int mi = 0; mi < 4; mi++)
                    mma_tf32(acc[mi][nj], af[mi], bf);
            }
        }
        __syncthreads();
    }

#pragma unroll
    for (int mi = 0; mi < 4; mi++) {
        int r = m0 + wm + mi * 16 + grp;
#pragma unroll
        for (int nj = 0; nj < 4; nj++) {
            int c = n0 + wn + nj * 8 + 2 * tid4;
            float bb0 = 0.f, bb1 = 0.f;
            if (bias) { bb0 = bias[c]; bb1 = bias[c + 1]; }
            float2 v0 = make_float2(fmaf(alpha, acc[mi][nj][0], bb0),
                                    fmaf(alpha, acc[mi][nj][1], bb1));
            float2 v1 = make_float2(fmaf(alpha, acc[mi][nj][2], bb0),
                                    fmaf(alpha, acc[mi][nj][3], bb1));
            *(float2*)&Cb[(long)r * ldc + c]       = v0;
            *(float2*)&Cb[(long)(r + 8) * ldc + c] = v1;
        }
    }
}

// ---------------------------------------------------------------------------
// attnv tf32: block (l-tile, hp, sp): 128(l) x 128(d of heads 2hp,2hp+1)
// unnormalized O-partials over P-chunk sp. Dual E planes; warp's 32-col
// range lies in one head (wn<64 -> head 2hp). Same mma core as tgemm_nt.
// ---------------------------------------------------------------------------
__global__ __launch_bounds__(256) void attnv_tf32(
    const float* __restrict__ E, const float* __restrict__ V,
    float* __restrict__ Opart)
{
    __shared__ unsigned As0[16][132];
    __shared__ unsigned As1[16][132];
    __shared__ unsigned Bs[16][132];

    const int hp = blockIdx.y;
    const int m0 = blockIdx.x * 128;
    const int sp = blockIdx.z;
    const float* Eh0 = E + (long)(2 * hp)     * ((long)LQ * PK);
    const float* Eh1 = E + (long)(2 * hp + 1) * ((long)LQ * PK);

    const int t    = threadIdx.x;
    const int w    = t >> 5;
    const int lane = t & 31;
    const int grp  = lane >> 2;
    const int tid4 = lane & 3;
    const int wm = (w & 1) * 64;
    const int wn = (w >> 1) * 32;

    const int srow = t >> 1;
    const int sk   = (t & 1) * 8;
    const int bkr  = t >> 4;        // 0..15 (k row for B staging)
    const int bnc  = (t & 15) * 8;  // 0..120 (n col for B staging)

    float acc[4][4][4];
#pragma unroll
    for (int mi = 0; mi < 4; mi++)
#pragma unroll
        for (int nj = 0; nj < 4; nj++)
#pragma unroll
            for (int q = 0; q < 4; q++) acc[mi][nj][q] = 0.0f;

    const float* a0Ptr = Eh0 + (long)(m0 + srow) * PK + sp * CHUNK + sk;
    const float* a1Ptr = Eh1 + (long)(m0 + srow) * PK + sp * CHUNK + sk;
    const float* bPtr  = V + (long)(sp * CHUNK + bkr) * DM + hp * 128 + bnc;

    const unsigned (*Ap)[132] = (wn < 64) ? As0 : As1;
    const int wnl = wn;  // block-local column base (0..96)

    for (int k0 = 0; k0 < CHUNK; k0 += 16) {
        float4 p00 = *(const float4*)(a0Ptr + k0);
        float4 p01 = *(const float4*)(a0Ptr + k0 + 4);
        float4 p10 = *(const float4*)(a1Ptr + k0);
        float4 p11 = *(const float4*)(a1Ptr + k0 + 4);
        float4 bv0 = *(const float4*)(bPtr + (long)k0 * DM);
        float4 bv1 = *(const float4*)(bPtr + (long)k0 * DM + 4);
        As0[sk + 0][srow] = f2tf(p00.x); As0[sk + 1][srow] = f2tf(p00.y);
        As0[sk + 2][srow] = f2tf(p00.z); As0[sk + 3][srow] = f2tf(p00.w);
        As0[sk + 4][srow] = f2tf(p01.x); As0[sk + 5][srow] = f2tf(p01.y);
        As0[sk + 6][srow] = f2tf(p01.z); As0[sk + 7][srow] = f2tf(p01.w);
        As1[sk + 0][srow] = f2tf(p10.x); As1[sk + 1][srow] = f2tf(p10.y);
        As1[sk + 2][srow] = f2tf(p10.z); As1[sk + 3][srow] = f2tf(p10.w);
        As1[sk + 4][srow] = f2tf(p11.x); As1[sk + 5][srow] = f2tf(p11.y);
        As1[sk + 6][srow] = f2tf(p11.z); As1[sk + 7][srow] = f2tf(p11.w);
        Bs[bkr][bnc + 0] = f2tf(bv0.x); Bs[bkr][bnc + 1] = f2tf(bv0.y);
        Bs[bkr][bnc + 2] = f2tf(bv0.z); Bs[bkr][bnc + 3] = f2tf(bv0.w);
        Bs[bkr][bnc + 4] = f2tf(bv1.x); Bs[bkr][bnc + 5] = f2tf(bv1.y);
        Bs[bkr][bnc + 6] = f2tf(bv1.z); Bs[bkr][bnc + 7] = f2tf(bv1.w);
        __syncthreads();

#pragma unroll
        for (int ks = 0; ks < 16; ks += 8) {
            unsigned af[4][4];
#pragma unroll
            for (int mi = 0; mi < 4; mi++) {
                int mb = wm + mi * 16;
                af[mi][0] = Ap[ks + tid4][mb + grp];
                af[mi][1] = Ap[ks + tid4][mb + 8 + grp];
                af[mi][2] = Ap[ks + 4 + tid4][mb + grp];
                af[mi][3] = Ap[ks + 4 + tid4][mb + 8 + grp];
            }
#pragma unroll
            for (int nj = 0; nj < 4; nj++) {
                unsigned bf[2];
                bf[0] = Bs[ks + tid4][wnl + nj * 8 + grp];
                bf[1] = Bs[ks + 4 + tid4][wnl + nj * 8 + grp];
#pragma unroll
                for (int mi = 0; mi < 4; mi++)
                    mma_tf32(acc[mi][nj], af[mi], bf);
            }
        }
        __syncthreads();
    }

    float* Ob = Opart + (long)sp * ((long)LQ * DM);
#pragma unroll
    for (int mi = 0; mi < 4; mi++) {
        int r = m0 + wm + mi * 16 + grp;
#pragma unroll
        for (int nj = 0; nj < 4; nj++) {
            int c = hp * 128 + wnl + nj * 8 + 2 * tid4;
            *(float2*)&Ob[(long)r * DM + c] =
                make_float2(acc[mi][nj][0], acc[mi][nj][1]);
            *(float2*)&Ob[(long)(r + 8) * DM + c] =
                make_float2(acc[mi][nj][2], acc[mi][nj][3]);
        }
    }
}

// ---------------------------------------------------------------------------
// bias_exp_v3 (unchanged, verified): grid (LQ, PSPLIT), cp.async double-buffer.
// ---------------------------------------------------------------------------
extern __shared__ float db_buf[];  // 2 * TPB * NR floats = 51.2 KB

__global__ __launch_bounds__(256) void bias_exp_v3(
    const float* __restrict__ rbf, const float* __restrict__ Wr,
    const float* __restrict__ br, float* __restrict__ S,
    float* __restrict__ Zp)
{
    __shared__ float wr_s[16 * 32];
    __shared__ float br_s[NH];
    __shared__ float zpart[8][NH];

    const int l    = blockIdx.x;
    const int pc   = blockIdx.y;
    const int t    = threadIdx.x;
    const int w    = t >> 5;
    const int lane = t & 31;
    const int row  = lane >> 1;
    const int half = lane & 1;

    for (int i = t; i < 16 * 32; i += 256) wr_s[i] = 0.0f;
    __syncthreads();
    for (int i = t; i < NH * NR; i += 256) {
        int h = i / NR, rr = i % NR;
        wr_s[(h * 2 + rr / 25) * 32 + (rr % 25)] = Wr[i];
    }
    if (t < NH) br_s[t] = br[t];

    const float* rbf_base = rbf + (long)l * PK * NR + (long)pc * PCH * NR;
    float* buf0 = db_buf;
    float* buf1 = db_buf + TPB * NR;
    const int NOPS = TPB * NR / 4;

    for (int i = t; i < NOPS; i += 256)
        cp16(buf0 + i * 4, rbf_base + (long)i * 4);
    cp_commit();

    float zacc[4] = {0.f, 0.f, 0.f, 0.f};
    const long lp = (long)l * PK;
    const int NT = PCH / TPB;

    for (int tile = 0; tile < NT; tile++) {
        float* cur = (tile & 1) ? buf1 : buf0;
        float* nxt = (tile & 1) ? buf0 : buf1;

        cp_wait_all();
        __syncthreads();

        if (tile + 1 < NT) {
            const float* src = rbf_base + (long)(tile + 1) * TPB * NR;
            for (int i = t; i < NOPS; i += 256)
                cp16(nxt + i * 4, src + (long)i * 4);
            cp_commit();
        }

        const float* rrow = cur + (w * 16 + row) * NR + half * 25;
        float rv[28];
#pragma unroll
        for (int r = 0; r < 25; r++) rv[r] = rrow[r];
        rv[25] = rv[26] = rv[27] = 0.0f;

        float acc[8];
#pragma unroll
        for (int h = 0; h < 8; h++) {
            const float4* wp = (const float4*)&wr_s[(h * 2 + half) * 32];
            float a0 = 0.f, a1 = 0.f, a2 = 0.f, a3 = 0.f;
#pragma unroll
            for (int q = 0; q < 7; q++) {
                float4 wv = wp[q];
                a0 = fmaf(rv[q * 4 + 0], wv.x, a0);
                a1 = fmaf(rv[q * 4 + 1], wv.y, a1);
                a2 = fmaf(rv[q * 4 + 2], wv.z, a2);
                a3 = fmaf(rv[q * 4 + 3], wv.w, a3);
            }
            acc[h] = (a0 + a1) + (a2 + a3);
        }

#pragma unroll
        for (int h = 0; h < 8; h++)
            acc[h] += __shfl_xor_sync(0xFFFFFFFFu, acc[h], 1);

        const int p = pc * PCH + tile * TPB + w * 16 + row;
#pragma unroll
        for (int j = 0; j < 4; j++) {
            const int h = half * 4 + j;
            float av = half ? acc[4 + j] : acc[j];
            float* ptr = S + (long)h * ((long)LQ * PK) + lp + p;
            float e = __expf(*ptr + av + br_s[h]);
            *ptr = e;
            zacc[j] += e;
        }
    }

#pragma unroll
    for (int j = 0; j < 4; j++) {
#pragma unroll
        for (int o = 2; o <= 16; o <<= 1)
            zacc[j] += __shfl_xor_sync(0xFFFFFFFFu, zacc[j], o);
    }
    if (lane < 2) {
#pragma unroll
        for (int j = 0; j < 4; j++) zpart[w][lane * 4 + j] = zacc[j];
    }
    __syncthreads();
    if (t < NH) {
        float s = 0.f;
#pragma unroll
        for (int ww = 0; ww < 8; ww++) s += zpart[ww][t];
        Zp[((long)pc * LQ + l) * NH + t] = s;
    }
}

// ---------------------------------------------------------------------------
__global__ __launch_bounds__(256) void rz_finalize(
    const float* __restrict__ Zp, float* __restrict__ rZ)
{
    const int i = blockIdx.x * 256 + threadIdx.x;
    float s = 0.f;
#pragma unroll
    for (int c = 0; c < PSPLIT; c++) s += Zp[(long)c * LQ * NH + i];
    rZ[i] = 1.0f / s;
}

// ---------------------------------------------------------------------------
__global__ __launch_bounds__(256) void attnv_reduce(
    const float* __restrict__ Opart, const float* __restrict__ rZ,
    float* __restrict__ O)
{
    const int idx = blockIdx.x * 256 + threadIdx.x;
    const int l  = idx / (DM / 4);
    const int d4 = idx % (DM / 4);
    const int h  = d4 / (DH / 4);

    float4 s = make_float4(0.f, 0.f, 0.f, 0.f);
#pragma unroll
    for (int sp = 0; sp < SPLIT; sp++) {
        float4 v = *(const float4*)(Opart + (long)sp * ((long)LQ * DM) + (long)idx * 4);
        s.x += v.x; s.y += v.y; s.z += v.z; s.w += v.w;
    }
    const float sc = rZ[l * NH + h];
    s.x *= sc; s.y *= sc; s.z *= sc; s.w *= sc;
    *(float4*)(O + (long)idx * 4) = s;
}

// ---------------------------------------------------------------------------
__global__ __launch_bounds__(256) void attn_mean_kernel(
    const float* __restrict__ E, const float* __restrict__ rZ,
    float* __restrict__ out)
{
    __shared__ float rz[NH];
    const int l = blockIdx.x >> 4;
    const int p = ((blockIdx.x & 15) << 8) + threadIdx.x;
    if (threadIdx.x < NH) rz[threadIdx.x] = rZ[l * NH + threadIdx.x];
    __syncthreads();

    const float* El = E + (long)l * PK + p;
    float s = 0.0f;
#pragma unroll
    for (int h = 0; h < NH; h++)
        s = fmaf(El[(long)h * ((long)LQ * PK)], rz[h], s);
    out[(long)l * PK + p] = s * 0.125f;
}

// ---------------------------------------------------------------------------
__global__ __launch_bounds__(256) void ln_kernel(
    const float* __restrict__ query, const float* __restrict__ Xo,
    const float* __restrict__ gamma, const float* __restrict__ beta,
    float* __restrict__ y)
{
    __shared__ float rs[8], rq[8];
    const int l = blockIdx.x;
    const int t = threadIdx.x;
    const int lane = t & 31, warp = t >> 5;

    float2 q  = *(const float2*)(query + (long)l * DM + t * 2);
    float2 xo = *(const float2*)(Xo    + (long)l * DM + t * 2);
    float x0 = q.x + xo.x;
    float x1 = q.y + xo.y;

    float s  = x0 + x1;
    float sq = x0 * x0 + x1 * x1;
#pragma unroll
    for (int o = 16; o > 0; o >>= 1) {
        s  += __shfl_xor_sync(0xFFFFFFFFu, s, o);
        sq += __shfl_xor_sync(0xFFFFFFFFu, sq, o);
    }
    if (lane == 0) { rs[warp] = s; rq[warp] = sq; }
    __syncthreads();
    if (warp == 0) {
        float a = (lane < 8) ? rs[lane] : 0.0f;
        float b = (lane < 8) ? rq[lane] : 0.0f;
#pragma unroll
        for (int o = 4; o > 0; o >>= 1) {
            a += __shfl_xor_sync(0xFFFFFFFFu, a, o);
            b += __shfl_xor_sync(0xFFFFFFFFu, b, o);
        }
        if (lane == 0) { rs[0] = a; rq[0] = b; }
    }
    __syncthreads();

    const float mean = rs[0] * (1.0f / DM);
    const float var  = rq[0] * (1.0f / DM) - mean * mean;
    const float rstd = rsqrtf(var + 1e-5f);

    float2 g = *(const float2*)(gamma + t * 2);
    float2 b = *(const float2*)(beta + t * 2);
    float2 o;
    o.x = (x0 - mean) * rstd * g.x + b.x;
    o.y = (x1 - mean) * rstd * g.y + b.y;
    *(float2*)(y + (long)l * DM + t * 2) = o;
}

// ---------------------------------------------------------------------------
extern "C" void kernel_launch(void* const* d_in, const int* in_sizes, int n_in,
                              void* d_out, int out_size)
{
    const float* query = (const float*)d_in[0];
    const float* key   = (const float*)d_in[1];
    const float* value = (const float*)d_in[2];
    const float* rbf   = (const float*)d_in[3];
    const float* Wq = (const float*)d_in[4];
    const float* bq = (const float*)d_in[5];
    const float* Wk = (const float*)d_in[6];
    const float* bk = (const float*)d_in[7];
    const float* Wv = (const float*)d_in[8];
    const float* bv = (const float*)d_in[9];
    const float* Wr = (const float*)d_in[10];
    const float* br = (const float*)d_in[11];
    const float* Wo = (const float*)d_in[12];
    const float* bo = (const float*)d_in[13];
    const float* gamma = (const float*)d_in[14];
    const float* beta  = (const float*)d_in[15];
    float* out = (float*)d_out;

    float *Qp, *Kp, *Vp, *S, *Zp, *rZ, *O, *Op, *Xo;
    cudaGetSymbolAddress((void**)&Qp, g_Qp);
    cudaGetSymbolAddress((void**)&Kp, g_Kp);
    cudaGetSymbolAddress((void**)&Vp, g_Vp);
    cudaGetSymbolAddress((void**)&S,  g_S);
    cudaGetSymbolAddress((void**)&Zp, g_Zp);
    cudaGetSymbolAddress((void**)&rZ, g_rZ);
    cudaGetSymbolAddress((void**)&O,  g_O);
    cudaGetSymbolAddress((void**)&Op, g_Op);
    cudaGetSymbolAddress((void**)&Xo, g_Xo);

    const int dynsmem = 2 * TPB * NR * sizeof(float);
    cudaFuncSetAttribute(bias_exp_v3, cudaFuncAttributeMaxDynamicSharedMemorySize,
                         dynsmem);

    // Projections: X @ W^T + b  (tf32 NT gemm, K=512)
    tgemm_nt<<<dim3(DM / 128, LQ / 128, 1), 256>>>(query, DM, 0, Wq, DM, 0,
                                                   Qp, DM, 0, DM, 1.0f, bq);
    tgemm_nt<<<dim3(DM / 128, PK / 128, 1), 256>>>(key, DM, 0, Wk, DM, 0,
                                                   Kp, DM, 0, DM, 1.0f, bk);
    tgemm_nt<<<dim3(DM / 128, PK / 128, 1), 256>>>(value, DM, 0, Wv, DM, 0,
                                                   Vp, DM, 0, DM, 1.0f, bv);

    // Scores: per head, S[h][l][p] = 0.125 * Q_h[l,:] . K_h[p,:]  (K=64)
    tgemm_nt<<<dim3(PK / 128, LQ / 128, NH), 256>>>(Qp, DM, DH, Kp, DM, DH,
                                                    S, PK, (long)LQ * PK,
                                                    DH, 0.125f, nullptr);

    // bias from cross_rbf + exp + per-(l,h,chunk) Z partials
    bias_exp_v3<<<dim3(LQ, PSPLIT), 256, dynsmem>>>(rbf, Wr, br, S, Zp);
    rz_finalize<<<(LQ * NH) / 256, 256>>>(Zp, rZ);

    // attn @ V (tf32, head pairs, split-K), then reduce + 1/Z
    attnv_tf32<<<dim3(LQ / 128, NH / 2, SPLIT), 256>>>(S, Vp, Op);
    attnv_reduce<<<(LQ * DM / 4) / 256, 256>>>(Op, rZ, O);

    // attn.mean over heads -> second output
    attn_mean_kernel<<<LQ * (PK / 256), 256>>>(S, rZ, out + (long)LQ * DM);

    // output projection (tf32)
    tgemm_nt<<<dim3(DM / 128, LQ / 128, 1), 256>>>(O, DM, 0, Wo, DM, 0,
                                                   Xo, DM, 0, DM, 1.0f, bo);

    // residual + layernorm -> first output
    ln_kernel<<<LQ, 256>>>(query, Xo, gamma, beta, out);
}

// round 14
// speedup vs baseline: 2.2245x; 1.4101x over previous
#include <cuda_runtime.h>
#include <cstdint>
#include <math.h>

#define LQ 1024
#define PK 4096
#define DM 512
#define NH 8
#define DH 64
#define NR 50
#define TPB 128            // p-tile for bias_exp
#define PSPLIT 4           // p-chunk split for bias_exp
#define PCH (PK / PSPLIT)  // 1024
#define SPLIT 8            // split-K factor for attnv
#define CHUNK (PK / SPLIT) // 512

// ---------------- scratch (device globals; no allocations allowed) ----------
__device__ float g_Qp[LQ * DM];            // 2 MB
__device__ float g_Kp[PK * DM];            // 8 MB
__device__ float g_Vp[PK * DM];            // 8 MB
__device__ float g_S[NH * LQ * PK];        // 134 MB  logits -> exp(logits), [H][L][P]
__device__ float g_Zp[PSPLIT * LQ * NH];   // Z partials per p-chunk
__device__ float g_rZ[LQ * NH];            // 1/Z per (l,h)
__device__ float g_O[LQ * DM];             // attention output (pre out-proj)
__device__ float g_Op[SPLIT * LQ * DM];    // 16 MB   split-K partials
__device__ float g_Xo[LQ * DM];            // out-proj result

// ---------------- cp.async helpers ----------------
__device__ __forceinline__ void cp16(void* smem_dst, const void* gmem_src) {
    unsigned s = (unsigned)__cvta_generic_to_shared(smem_dst);
    asm volatile("cp.async.cg.shared.global [%0], [%1], 16;" :: "r"(s), "l"(gmem_src));
}
__device__ __forceinline__ void cp_commit() {
    asm volatile("cp.async.commit_group;" ::: "memory");
}
__device__ __forceinline__ void cp_wait_all() {
    asm volatile("cp.async.wait_group 0;" ::: "memory");
}

// ---------------- tf32 mma helpers ----------------
__device__ __forceinline__ unsigned f2tf(float x) {
    unsigned r;
    asm("cvt.rna.tf32.f32 %0, %1;" : "=r"(r) : "f"(x));
    return r;
}
__device__ __forceinline__ void mma_tf32(float* d, const unsigned* a,
                                         const unsigned* b) {
    asm volatile(
        "mma.sync.aligned.m16n8k8.row.col.f32.tf32.tf32.f32 "
        "{%0,%1,%2,%3}, {%4,%5,%6,%7}, {%8,%9}, {%0,%1,%2,%3};\n"
        : "+f"(d[0]), "+f"(d[1]), "+f"(d[2]), "+f"(d[3])
        : "r"(a[0]), "r"(a[1]), "r"(a[2]), "r"(a[3]),
          "r"(b[0]), "r"(b[1]));
}

// ---------------------------------------------------------------------------
// tf32 NT GEMM (verified in R12): C = alpha * A @ B^T (+ bias)
// ---------------------------------------------------------------------------
__global__ __launch_bounds__(256) void tgemm_nt(
    const float* __restrict__ A, int lda, int aStride,
    const float* __restrict__ B, int ldb, int bStride,
    float* __restrict__ C, int ldc, long cStride,
    int K, float alpha, const float* __restrict__ bias)
{
    __shared__ unsigned As[16][132];
    __shared__ unsigned Bs[16][132];

    const int bz = blockIdx.z;
    const float* Ab = A + (long)bz * aStride;
    const float* Bb = B + (long)bz * bStride;
    float* Cb = C + (long)bz * cStride;

    const int m0 = blockIdx.y * 128;
    const int n0 = blockIdx.x * 128;
    const int t    = threadIdx.x;
    const int w    = t >> 5;
    const int lane = t & 31;
    const int grp  = lane >> 2;
    const int tid4 = lane & 3;
    const int wm = (w & 1) * 64;
    const int wn = (w >> 1) * 32;

    const int srow = t >> 1;        // 0..127
    const int sk   = (t & 1) * 8;   // 0 or 8

    float acc[4][4][4];
#pragma unroll
    for (int mi = 0; mi < 4; mi++)
#pragma unroll
        for (int nj = 0; nj < 4; nj++)
#pragma unroll
            for (int q = 0; q < 4; q++) acc[mi][nj][q] = 0.0f;

    const float* aPtr = Ab + (long)(m0 + srow) * lda + sk;
    const float* bPtr = Bb + (long)(n0 + srow) * ldb + sk;

    for (int k0 = 0; k0 < K; k0 += 16) {
        float4 a0v = *(const float4*)(aPtr + k0);
        float4 a1v = *(const float4*)(aPtr + k0 + 4);
        float4 b0v = *(const float4*)(bPtr + k0);
        float4 b1v = *(const float4*)(bPtr + k0 + 4);
        As[sk + 0][srow] = f2tf(a0v.x); As[sk + 1][srow] = f2tf(a0v.y);
        As[sk + 2][srow] = f2tf(a0v.z); As[sk + 3][srow] = f2tf(a0v.w);
        As[sk + 4][srow] = f2tf(a1v.x); As[sk + 5][srow] = f2tf(a1v.y);
        As[sk + 6][srow] = f2tf(a1v.z); As[sk + 7][srow] = f2tf(a1v.w);
        Bs[sk + 0][srow] = f2tf(b0v.x); Bs[sk + 1][srow] = f2tf(b0v.y);
        Bs[sk + 2][srow] = f2tf(b0v.z); Bs[sk + 3][srow] = f2tf(b0v.w);
        Bs[sk + 4][srow] = f2tf(b1v.x); Bs[sk + 5][srow] = f2tf(b1v.y);
        Bs[sk + 6][srow] = f2tf(b1v.z); Bs[sk + 7][srow] = f2tf(b1v.w);
        __syncthreads();

#pragma unroll
        for (int ks = 0; ks < 16; ks += 8) {
            unsigned af[4][4];
#pragma unroll
            for (int mi = 0; mi < 4; mi++) {
                int mb = wm + mi * 16;
                af[mi][0] = As[ks + tid4][mb + grp];
                af[mi][1] = As[ks + tid4][mb + 8 + grp];
                af[mi][2] = As[ks + 4 + tid4][mb + grp];
                af[mi][3] = As[ks + 4 + tid4][mb + 8 + grp];
            }
#pragma unroll
            for (int nj = 0; nj < 4; nj++) {
                unsigned bf[2];
                bf[0] = Bs[ks + tid4][wn + nj * 8 + grp];
                bf[1] = Bs[ks + 4 + tid4][wn + nj * 8 + grp];
#pragma unroll
                for (int mi = 0; mi < 4; mi++)
                    mma_tf32(acc[mi][nj], af[mi], bf);
            }
        }
        __syncthreads();
    }

#pragma unroll
    for (int mi = 0; mi < 4; mi++) {
        int r = m0 + wm + mi * 16 + grp;
#pragma unroll
        for (int nj = 0; nj < 4; nj++) {
            int c = n0 + wn + nj * 8 + 2 * tid4;
            float bb0 = 0.f, bb1 = 0.f;
            if (bias) { bb0 = bias[c]; bb1 = bias[c + 1]; }
            float2 v0 = make_float2(fmaf(alpha, acc[mi][nj][0], bb0),
                                    fmaf(alpha, acc[mi][nj][1], bb1));
            float2 v1 = make_float2(fmaf(alpha, acc[mi][nj][2], bb0),
                                    fmaf(alpha, acc[mi][nj][3], bb1));
            *(float2*)&Cb[(long)r * ldc + c]       = v0;
            *(float2*)&Cb[(long)(r + 8) * ldc + c] = v1;
        }
    }
}

// ---------------------------------------------------------------------------
// attnv tf32 (verified in R12): head-pair tiles + split-K.
// ---------------------------------------------------------------------------
__global__ __launch_bounds__(256) void attnv_tf32(
    const float* __restrict__ E, const float* __restrict__ V,
    float* __restrict__ Opart)
{
    __shared__ unsigned As0[16][132];
    __shared__ unsigned As1[16][132];
    __shared__ unsigned Bs[16][132];

    const int hp = blockIdx.y;
    const int m0 = blockIdx.x * 128;
    const int sp = blockIdx.z;
    const float* Eh0 = E + (long)(2 * hp)     * ((long)LQ * PK);
    const float* Eh1 = E + (long)(2 * hp + 1) * ((long)LQ * PK);

    const int t    = threadIdx.x;
    const int w    = t >> 5;
    const int lane = t & 31;
    const int grp  = lane >> 2;
    const int tid4 = lane & 3;
    const int wm = (w & 1) * 64;
    const int wn = (w >> 1) * 32;

    const int srow = t >> 1;
    const int sk   = (t & 1) * 8;
    const int bkr  = t >> 4;
    const int bnc  = (t & 15) * 8;

    float acc[4][4][4];
#pragma unroll
    for (int mi = 0; mi < 4; mi++)
#pragma unroll
        for (int nj = 0; nj < 4; nj++)
#pragma unroll
            for (int q = 0; q < 4; q++) acc[mi][nj][q] = 0.0f;

    const float* a0Ptr = Eh0 + (long)(m0 + srow) * PK + sp * CHUNK + sk;
    const float* a1Ptr = Eh1 + (long)(m0 + srow) * PK + sp * CHUNK + sk;
    const float* bPtr  = V + (long)(sp * CHUNK + bkr) * DM + hp * 128 + bnc;

    const unsigned (*Ap)[132] = (wn < 64) ? As0 : As1;
    const int wnl = wn;

    for (int k0 = 0; k0 < CHUNK; k0 += 16) {
        float4 p00 = *(const float4*)(a0Ptr + k0);
        float4 p01 = *(const float4*)(a0Ptr + k0 + 4);
        float4 p10 = *(const float4*)(a1Ptr + k0);
        float4 p11 = *(const float4*)(a1Ptr + k0 + 4);
        float4 bv0 = *(const float4*)(bPtr + (long)k0 * DM);
        float4 bv1 = *(const float4*)(bPtr + (long)k0 * DM + 4);
        As0[sk + 0][srow] = f2tf(p00.x); As0[sk + 1][srow] = f2tf(p00.y);
        As0[sk + 2][srow] = f2tf(p00.z); As0[sk + 3][srow] = f2tf(p00.w);
        As0[sk + 4][srow] = f2tf(p01.x); As0[sk + 5][srow] = f2tf(p01.y);
        As0[sk + 6][srow] = f2tf(p01.z); As0[sk + 7][srow] = f2tf(p01.w);
        As1[sk + 0][srow] = f2tf(p10.x); As1[sk + 1][srow] = f2tf(p10.y);
        As1[sk + 2][srow] = f2tf(p10.z); As1[sk + 3][srow] = f2tf(p10.w);
        As1[sk + 4][srow] = f2tf(p11.x); As1[sk + 5][srow] = f2tf(p11.y);
        As1[sk + 6][srow] = f2tf(p11.z); As1[sk + 7][srow] = f2tf(p11.w);
        Bs[bkr][bnc + 0] = f2tf(bv0.x); Bs[bkr][bnc + 1] = f2tf(bv0.y);
        Bs[bkr][bnc + 2] = f2tf(bv0.z); Bs[bkr][bnc + 3] = f2tf(bv0.w);
        Bs[bkr][bnc + 4] = f2tf(bv1.x); Bs[bkr][bnc + 5] = f2tf(bv1.y);
        Bs[bkr][bnc + 6] = f2tf(bv1.z); Bs[bkr][bnc + 7] = f2tf(bv1.w);
        __syncthreads();

#pragma unroll
        for (int ks = 0; ks < 16; ks += 8) {
            unsigned af[4][4];
#pragma unroll
            for (int mi = 0; mi < 4; mi++) {
                int mb = wm + mi * 16;
                af[mi][0] = Ap[ks + tid4][mb + grp];
                af[mi][1] = Ap[ks + tid4][mb + 8 + grp];
                af[mi][2] = Ap[ks + 4 + tid4][mb + grp];
                af[mi][3] = Ap[ks + 4 + tid4][mb + 8 + grp];
            }
#pragma unroll
            for (int nj = 0; nj < 4; nj++) {
                unsigned bf[2];
                bf[0] = Bs[ks + tid4][wnl + nj * 8 + grp];
                bf[1] = Bs[ks + 4 + tid4][wnl + nj * 8 + grp];
#pragma unroll
                for (int mi = 0; mi < 4; mi++)
                    mma_tf32(acc[mi][nj], af[mi], bf);
            }
        }
        __syncthreads();
    }

    float* Ob = Opart + (long)sp * ((long)LQ * DM);
#pragma unroll
    for (int mi = 0; mi < 4; mi++) {
        int r = m0 + wm + mi * 16 + grp;
#pragma unroll
        for (int nj = 0; nj < 4; nj++) {
            int c = hp * 128 + wnl + nj * 8 + 2 * tid4;
            *(float2*)&Ob[(long)r * DM + c] =
                make_float2(acc[mi][nj][0], acc[mi][nj][1]);
            *(float2*)&Ob[(long)(r + 8) * DM + c] =
                make_float2(acc[mi][nj][2], acc[mi][nj][3]);
        }
    }
}

// ---------------------------------------------------------------------------
// bias_exp_v4: bias dot-products on TENSOR CORES.
// grid (LQ, PSPLIT), 256 thr = 8 warps. Tile = 128 p; warp w owns the m16
// fragment of p-rows [w*16, w*16+16). rbf tile kept FLAT in smem ([p*50+r],
// cp.async double-buffered as in v3). Bias = mma m16n8k8: M=p, N=8 heads,
// K=50 padded to 56 (7 k-steps; tails zeroed via Wr-side zeros, compile-time
// per step). C-fragment: thread owns (p=w16+g, h=2t4), (p, h=2t4+1),
// (p+8, h=2t4), (p+8, h=2t4+1) -> S read-mod-write + exp + Z like v3.
// ---------------------------------------------------------------------------
extern __shared__ float db_buf[];  // 2 * TPB * NR floats = 51.2 KB

__global__ __launch_bounds__(256) void bias_exp_v4(
    const float* __restrict__ rbf, const float* __restrict__ Wr,
    const float* __restrict__ br, float* __restrict__ S,
    float* __restrict__ Zp)
{
    __shared__ float zpart[8][NH];

    const int l    = blockIdx.x;
    const int pc   = blockIdx.y;
    const int t    = threadIdx.x;
    const int w    = t >> 5;
    const int lane = t & 31;
    const int g    = lane >> 2;   // 0..7: p-row within frag / head index for B
    const int t4   = lane & 3;    // k index within frag / head pair for C

    // --- Wr fragments (B operand), held in registers for the whole block ---
    // b value at (k, n=h=g) = Wr[g*NR + k], zero for k >= 50.
    unsigned bfr[7][2];
#pragma unroll
    for (int ks = 0; ks < 7; ks++) {
        int k0 = ks * 8 + t4;
        int k1 = k0 + 4;
        float w0 = (k0 < NR) ? Wr[g * NR + k0] : 0.0f;
        float w1 = (k1 < NR) ? Wr[g * NR + k1] : 0.0f;
        bfr[ks][0] = f2tf(w0);
        bfr[ks][1] = f2tf(w1);
    }
    const float brh0 = br[2 * t4];
    const float brh1 = br[2 * t4 + 1];

    const float* rbf_base = rbf + (long)l * PK * NR + (long)pc * PCH * NR;
    float* buf0 = db_buf;
    float* buf1 = db_buf + TPB * NR;
    const int NOPS = TPB * NR / 4;  // 1600

    // prologue: async-prefetch tile 0
    for (int i = t; i < NOPS; i += 256)
        cp16(buf0 + i * 4, rbf_base + (long)i * 4);
    cp_commit();

    float zacc0 = 0.f, zacc1 = 0.f;  // h = 2*t4, 2*t4+1
    const long lp = (long)l * PK;
    const int NT = PCH / TPB;  // 8

    for (int tile = 0; tile < NT; tile++) {
        float* cur = (tile & 1) ? buf1 : buf0;
        float* nxt = (tile & 1) ? buf0 : buf1;

        cp_wait_all();
        __syncthreads();

        if (tile + 1 < NT) {
            const float* src = rbf_base + (long)(tile + 1) * TPB * NR;
            for (int i = t; i < NOPS; i += 256)
                cp16(nxt + i * 4, src + (long)i * 4);
            cp_commit();
        }

        // --- bias mma: acc = rbf_tile(warp's 16 rows) @ Wr^T ---
        const float* r0 = cur + (w * 16 + g) * NR;      // row p = w16+g
        const float* r1 = r0 + 8 * NR;                  // row p+8
        float acc[4] = {0.f, 0.f, 0.f, 0.f};
#pragma unroll
        for (int ks = 0; ks < 7; ks++) {
            int k0 = ks * 8 + t4;
            int k1 = k0 + 4;
            unsigned af[4];
            // rbf side: truncation to tf32 via raw bits (values in [0,1], safe)
            af[0] = (k0 < NR) ? __float_as_uint(r0[k0]) : 0u;
            af[1] = (k0 < NR) ? __float_as_uint(r1[k0]) : 0u;
            af[2] = (k1 < NR) ? __float_as_uint(r0[k1]) : 0u;
            af[3] = (k1 < NR) ? __float_as_uint(r1[k1]) : 0u;
            mma_tf32(acc, af, bfr[ks]);
        }

        // --- S read-modify-write + exp + Z ---
        const int p  = pc * PCH + tile * TPB + w * 16 + g;
        const int h0 = 2 * t4;
        float* s00 = S + (long)h0 * ((long)LQ * PK) + lp + p;         // (p,   h0)
        float* s01 = s00 + (long)LQ * PK;                              // (p,   h0+1)
        float* s10 = s00 + 8;                                          // (p+8, h0)
        float* s11 = s01 + 8;                                          // (p+8, h0+1)

        float e00 = __expf(*s00 + acc[0] + brh0);
        float e01 = __expf(*s01 + acc[1] + brh1);
        float e10 = __expf(*s10 + acc[2] + brh0);
        float e11 = __expf(*s11 + acc[3] + brh1);
        *s00 = e00; *s01 = e01; *s10 = e10; *s11 = e11;
        zacc0 += e00 + e10;
        zacc1 += e01 + e11;
    }

    // reduce Z over g-lanes (same t4): shfl offsets 4,8,16 stay within t4 class
#pragma unroll
    for (int o = 4; o <= 16; o <<= 1) {
        zacc0 += __shfl_xor_sync(0xFFFFFFFFu, zacc0, o);
        zacc1 += __shfl_xor_sync(0xFFFFFFFFu, zacc1, o);
    }
    if (lane < 4) {  // lane == t4 (g == 0)
        zpart[w][2 * t4]     = zacc0;
        zpart[w][2 * t4 + 1] = zacc1;
    }
    __syncthreads();
    if (t < NH) {
        float s = 0.f;
#pragma unroll
        for (int ww = 0; ww < 8; ww++) s += zpart[ww][t];
        Zp[((long)pc * LQ + l) * NH + t] = s;
    }
}

// ---------------------------------------------------------------------------
__global__ __launch_bounds__(256) void rz_finalize(
    const float* __restrict__ Zp, float* __restrict__ rZ)
{
    const int i = blockIdx.x * 256 + threadIdx.x;
    float s = 0.f;
#pragma unroll
    for (int c = 0; c < PSPLIT; c++) s += Zp[(long)c * LQ * NH + i];
    rZ[i] = 1.0f / s;
}

// ---------------------------------------------------------------------------
__global__ __launch_bounds__(256) void attnv_reduce(
    const float* __restrict__ Opart, const float* __restrict__ rZ,
    float* __restrict__ O)
{
    const int idx = blockIdx.x * 256 + threadIdx.x;
    const int l  = idx / (DM / 4);
    const int d4 = idx % (DM / 4);
    const int h  = d4 / (DH / 4);

    float4 s = make_float4(0.f, 0.f, 0.f, 0.f);
#pragma unroll
    for (int sp = 0; sp < SPLIT; sp++) {
        float4 v = *(const float4*)(Opart + (long)sp * ((long)LQ * DM) + (long)idx * 4);
        s.x += v.x; s.y += v.y; s.z += v.z; s.w += v.w;
    }
    const float sc = rZ[l * NH + h];
    s.x *= sc; s.y *= sc; s.z *= sc; s.w *= sc;
    *(float4*)(O + (long)idx * 4) = s;
}

// ---------------------------------------------------------------------------
__global__ __launch_bounds__(256) void attn_mean_kernel(
    const float* __restrict__ E, const float* __restrict__ rZ,
    float* __restrict__ out)
{
    __shared__ float rz[NH];
    const int l = blockIdx.x >> 4;
    const int p = ((blockIdx.x & 15) << 8) + threadIdx.x;
    if (threadIdx.x < NH) rz[threadIdx.x] = rZ[l * NH + threadIdx.x];
    __syncthreads();

    const float* El = E + (long)l * PK + p;
    float s = 0.0f;
#pragma unroll
    for (int h = 0; h < NH; h++)
        s = fmaf(El[(long)h * ((long)LQ * PK)], rz[h], s);
    out[(long)l * PK + p] = s * 0.125f;
}

// ---------------------------------------------------------------------------
__global__ __launch_bounds__(256) void ln_kernel(
    const float* __restrict__ query, const float* __restrict__ Xo,
    const float* __restrict__ gamma, const float* __restrict__ beta,
    float* __restrict__ y)
{
    __shared__ float rs[8], rq[8];
    const int l = blockIdx.x;
    const int t = threadIdx.x;
    const int lane = t & 31, warp = t >> 5;

    float2 q  = *(const float2*)(query + (long)l * DM + t * 2);
    float2 xo = *(const float2*)(Xo    + (long)l * DM + t * 2);
    float x0 = q.x + xo.x;
    float x1 = q.y + xo.y;

    float s  = x0 + x1;
    float sq = x0 * x0 + x1 * x1;
#pragma unroll
    for (int o = 16; o > 0; o >>= 1) {
        s  += __shfl_xor_sync(0xFFFFFFFFu, s, o);
        sq += __shfl_xor_sync(0xFFFFFFFFu, sq, o);
    }
    if (lane == 0) { rs[warp] = s; rq[warp] = sq; }
    __syncthreads();
    if (warp == 0) {
        float a = (lane < 8) ? rs[lane] : 0.0f;
        float b = (lane < 8) ? rq[lane] : 0.0f;
#pragma unroll
        for (int o = 4; o > 0; o >>= 1) {
            a += __shfl_xor_sync(0xFFFFFFFFu, a, o);
            b += __shfl_xor_sync(0xFFFFFFFFu, b, o);
        }
        if (lane == 0) { rs[0] = a; rq[0] = b; }
    }
    __syncthreads();

    const float mean = rs[0] * (1.0f / DM);
    const float var  = rq[0] * (1.0f / DM) - mean * mean;
    const float rstd = rsqrtf(var + 1e-5f);

    float2 g = *(const float2*)(gamma + t * 2);
    float2 b = *(const float2*)(beta + t * 2);
    float2 o;
    o.x = (x0 - mean) * rstd * g.x + b.x;
    o.y = (x1 - mean) * rstd * g.y + b.y;
    *(float2*)(y + (long)l * DM + t * 2) = o;
}

// ---------------------------------------------------------------------------
extern "C" void kernel_launch(void* const* d_in, const int* in_sizes, int n_in,
                              void* d_out, int out_size)
{
    const float* query = (const float*)d_in[0];
    const float* key   = (const float*)d_in[1];
    const float* value = (const float*)d_in[2];
    const float* rbf   = (const float*)d_in[3];
    const float* Wq = (const float*)d_in[4];
    const float* bq = (const float*)d_in[5];
    const float* Wk = (const float*)d_in[6];
    const float* bk = (const float*)d_in[7];
    const float* Wv = (const float*)d_in[8];
    const float* bv = (const float*)d_in[9];
    const float* Wr = (const float*)d_in[10];
    const float* br = (const float*)d_in[11];
    const float* Wo = (const float*)d_in[12];
    const float* bo = (const float*)d_in[13];
    const float* gamma = (const float*)d_in[14];
    const float* beta  = (const float*)d_in[15];
    float* out = (float*)d_out;

    float *Qp, *Kp, *Vp, *S, *Zp, *rZ, *O, *Op, *Xo;
    cudaGetSymbolAddress((void**)&Qp, g_Qp);
    cudaGetSymbolAddress((void**)&Kp, g_Kp);
    cudaGetSymbolAddress((void**)&Vp, g_Vp);
    cudaGetSymbolAddress((void**)&S,  g_S);
    cudaGetSymbolAddress((void**)&Zp, g_Zp);
    cudaGetSymbolAddress((void**)&rZ, g_rZ);
    cudaGetSymbolAddress((void**)&O,  g_O);
    cudaGetSymbolAddress((void**)&Op, g_Op);
    cudaGetSymbolAddress((void**)&Xo, g_Xo);

    const int dynsmem = 2 * TPB * NR * sizeof(float);
    cudaFuncSetAttribute(bias_exp_v4, cudaFuncAttributeMaxDynamicSharedMemorySize,
                         dynsmem);

    // Projections: X @ W^T + b  (tf32 NT gemm, K=512)
    tgemm_nt<<<dim3(DM / 128, LQ / 128, 1), 256>>>(query, DM, 0, Wq, DM, 0,
                                                   Qp, DM, 0, DM, 1.0f, bq);
    tgemm_nt<<<dim3(DM / 128, PK / 128, 1), 256>>>(key, DM, 0, Wk, DM, 0,
                                                   Kp, DM, 0, DM, 1.0f, bk);
    tgemm_nt<<<dim3(DM / 128, PK / 128, 1), 256>>>(value, DM, 0, Wv, DM, 0,
                                                   Vp, DM, 0, DM, 1.0f, bv);

    // Scores: per head, S[h][l][p] = 0.125 * Q_h[l,:] . K_h[p,:]  (K=64)
    tgemm_nt<<<dim3(PK / 128, LQ / 128, NH), 256>>>(Qp, DM, DH, Kp, DM, DH,
                                                    S, PK, (long)LQ * PK,
                                                    DH, 0.125f, nullptr);

    // bias from cross_rbf (tensor-core) + exp + per-(l,h,chunk) Z partials
    bias_exp_v4<<<dim3(LQ, PSPLIT), 256, dynsmem>>>(rbf, Wr, br, S, Zp);
    rz_finalize<<<(LQ * NH) / 256, 256>>>(Zp, rZ);

    // attn @ V (tf32, head pairs, split-K), then reduce + 1/Z
    attnv_tf32<<<dim3(LQ / 128, NH / 2, SPLIT), 256>>>(S, Vp, Op);
    attnv_reduce<<<(LQ * DM / 4) / 256, 256>>>(Op, rZ, O);

    // attn.mean over heads -> second output
    attn_mean_kernel<<<LQ * (PK / 256), 256>>>(S, rZ, out + (long)LQ * DM);

    // output projection (tf32)
    tgemm_nt<<<dim3(DM / 128, LQ / 128, 1), 256>>>(O, DM, 0, Wo, DM, 0,
                                                   Xo, DM, 0, DM, 1.0f, bo);

    // residual + layernorm -> first output
    ln_kernel<<<LQ, 256>>>(query, Xo, gamma, beta, out);
}

// round 16
// speedup vs baseline: 2.5147x; 1.1304x over previous
#include <cuda_runtime.h>
#include <cstdint>
#include <math.h>

#define LQ 1024
#define PK 4096
#define DM 512
#define NH 8
#define DH 64
#define NR 50
#define TPB 128            // p-tile for bias_exp
#define PSPLIT 8           // p-chunk split for bias_exp
#define PCH (PK / PSPLIT)  // 512
#define SPLIT 8            // split-K factor for attnv
#define CHUNK (PK / SPLIT) // 512

// ---------------- scratch (device globals; no allocations allowed) ----------
__device__ float g_Qp[LQ * DM];            // 2 MB
__device__ float g_Kp[PK * DM];            // 8 MB
__device__ float g_Vp[PK * DM];            // 8 MB
__device__ float g_S[NH * LQ * PK];        // 134 MB  logits -> exp(logits), [H][L][P]
__device__ float g_Zp[PSPLIT * LQ * NH];   // Z partials per p-chunk
__device__ float g_rZ[LQ * NH];            // 1/Z per (l,h)
__device__ float g_O[LQ * DM];             // attention output (pre out-proj)
__device__ float g_Op[SPLIT * LQ * DM];    // 16 MB   split-K partials
__device__ float g_Xo[LQ * DM];            // out-proj result

// ---------------- cp.async helpers ----------------
__device__ __forceinline__ void cp16(void* smem_dst, const void* gmem_src) {
    unsigned s = (unsigned)__cvta_generic_to_shared(smem_dst);
    asm volatile("cp.async.cg.shared.global [%0], [%1], 16;" :: "r"(s), "l"(gmem_src));
}
__device__ __forceinline__ void cp_commit() {
    asm volatile("cp.async.commit_group;" ::: "memory");
}
__device__ __forceinline__ void cp_wait_all() {
    asm volatile("cp.async.wait_group 0;" ::: "memory");
}

// ---------------- tf32 mma helpers ----------------
__device__ __forceinline__ unsigned f2tf(float x) {
    unsigned r;
    asm("cvt.rna.tf32.f32 %0, %1;" : "=r"(r) : "f"(x));
    return r;
}
__device__ __forceinline__ void mma_tf32(float* d, const unsigned* a,
                                         const unsigned* b) {
    asm volatile(
        "mma.sync.aligned.m16n8k8.row.col.f32.tf32.tf32.f32 "
        "{%0,%1,%2,%3}, {%4,%5,%6,%7}, {%8,%9}, {%0,%1,%2,%3};\n"
        : "+f"(d[0]), "+f"(d[1]), "+f"(d[2]), "+f"(d[3])
        : "r"(a[0]), "r"(a[1]), "r"(a[2]), "r"(a[3]),
          "r"(b[0]), "r"(b[1]));
}

// ---------------------------------------------------------------------------
// Shared tf32 GEMM block body: C128x128 tile at (m0, n0) of C = A@B^T + bias.
// lda = ldb = K assumed contiguous rows; 256 threads / 8 warps.
// ---------------------------------------------------------------------------
__device__ __forceinline__ void tgemm_block(
    const float* __restrict__ A, const float* __restrict__ B,
    float* __restrict__ C, int lda, int ldb, int ldc,
    int m0, int n0, int K, float alpha, const float* __restrict__ bias,
    unsigned (*As)[132], unsigned (*Bs)[132])
{
    const int t    = threadIdx.x;
    const int w    = t >> 5;
    const int lane = t & 31;
    const int grp  = lane >> 2;
    const int tid4 = lane & 3;
    const int wm = (w & 1) * 64;
    const int wn = (w >> 1) * 32;

    const int srow = t >> 1;
    const int sk   = (t & 1) * 8;

    float acc[4][4][4];
#pragma unroll
    for (int mi = 0; mi < 4; mi++)
#pragma unroll
        for (int nj = 0; nj < 4; nj++)
#pragma unroll
            for (int q = 0; q < 4; q++) acc[mi][nj][q] = 0.0f;

    const float* aPtr = A + (long)(m0 + srow) * lda + sk;
    const float* bPtr = B + (long)(n0 + srow) * ldb + sk;

    for (int k0 = 0; k0 < K; k0 += 16) {
        float4 a0v = *(const float4*)(aPtr + k0);
        float4 a1v = *(const float4*)(aPtr + k0 + 4);
        float4 b0v = *(const float4*)(bPtr + k0);
        float4 b1v = *(const float4*)(bPtr + k0 + 4);
        As[sk + 0][srow] = f2tf(a0v.x); As[sk + 1][srow] = f2tf(a0v.y);
        As[sk + 2][srow] = f2tf(a0v.z); As[sk + 3][srow] = f2tf(a0v.w);
        As[sk + 4][srow] = f2tf(a1v.x); As[sk + 5][srow] = f2tf(a1v.y);
        As[sk + 6][srow] = f2tf(a1v.z); As[sk + 7][srow] = f2tf(a1v.w);
        Bs[sk + 0][srow] = f2tf(b0v.x); Bs[sk + 1][srow] = f2tf(b0v.y);
        Bs[sk + 2][srow] = f2tf(b0v.z); Bs[sk + 3][srow] = f2tf(b0v.w);
        Bs[sk + 4][srow] = f2tf(b1v.x); Bs[sk + 5][srow] = f2tf(b1v.y);
        Bs[sk + 6][srow] = f2tf(b1v.z); Bs[sk + 7][srow] = f2tf(b1v.w);
        __syncthreads();

#pragma unroll
        for (int ks = 0; ks < 16; ks += 8) {
            unsigned af[4][4];
#pragma unroll
            for (int mi = 0; mi < 4; mi++) {
                int mb = wm + mi * 16;
                af[mi][0] = As[ks + tid4][mb + grp];
                af[mi][1] = As[ks + tid4][mb + 8 + grp];
                af[mi][2] = As[ks + 4 + tid4][mb + grp];
                af[mi][3] = As[ks + 4 + tid4][mb + 8 + grp];
            }
#pragma unroll
            for (int nj = 0; nj < 4; nj++) {
                unsigned bf[2];
                bf[0] = Bs[ks + tid4][wn + nj * 8 + grp];
                bf[1] = Bs[ks + 4 + tid4][wn + nj * 8 + grp];
#pragma unroll
                for (int mi = 0; mi < 4; mi++)
                    mma_tf32(acc[mi][nj], af[mi], bf);
            }
        }
        __syncthreads();
    }

#pragma unroll
    for (int mi = 0; mi < 4; mi++) {
        int r = m0 + wm + mi * 16 + grp;
#pragma unroll
        for (int nj = 0; nj < 4; nj++) {
            int c = n0 + wn + nj * 8 + 2 * tid4;
            float bb0 = 0.f, bb1 = 0.f;
            if (bias) { bb0 = bias[c]; bb1 = bias[c + 1]; }
            float2 v0 = make_float2(fmaf(alpha, acc[mi][nj][0], bb0),
                                    fmaf(alpha, acc[mi][nj][1], bb1));
            float2 v1 = make_float2(fmaf(alpha, acc[mi][nj][2], bb0),
                                    fmaf(alpha, acc[mi][nj][3], bb1));
            *(float2*)&C[(long)r * ldc + c]       = v0;
            *(float2*)&C[(long)(r + 8) * ldc + c] = v1;
        }
    }
}

// ---------------------------------------------------------------------------
// tf32 NT GEMM launcher kernel (verified core): batched via blockIdx.z.
// ---------------------------------------------------------------------------
__global__ __launch_bounds__(256) void tgemm_nt(
    const float* __restrict__ A, int lda, int aStride,
    const float* __restrict__ B, int ldb, int bStride,
    float* __restrict__ C, int ldc, long cStride,
    int K, float alpha, const float* __restrict__ bias)
{
    __shared__ unsigned As[16][132];
    __shared__ unsigned Bs[16][132];
    const int bz = blockIdx.z;
    tgemm_block(A + (long)bz * aStride, B + (long)bz * bStride,
                C + (long)bz * cStride, lda, ldb, ldc,
                blockIdx.y * 128, blockIdx.x * 128, K, alpha, bias, As, Bs);
}

// ---------------------------------------------------------------------------
// qkv_fused: ONE launch for all three projections (288 equal-work blocks).
//   blocks [0,32):    Qp = query @ Wq^T + bq   (8 m-tiles x 4 n-tiles)
//   blocks [32,160):  Kp = key   @ Wk^T + bk   (32 x 4)
//   blocks [160,288): Vp = value @ Wv^T + bv   (32 x 4)
// ---------------------------------------------------------------------------
__global__ __launch_bounds__(256) void qkv_fused(
    const float* __restrict__ q, const float* __restrict__ k,
    const float* __restrict__ v,
    const float* __restrict__ Wq, const float* __restrict__ Wk,
    const float* __restrict__ Wv,
    const float* __restrict__ bq, const float* __restrict__ bk,
    const float* __restrict__ bv,
    float* __restrict__ Qp, float* __restrict__ Kp, float* __restrict__ Vp)
{
    __shared__ unsigned As[16][132];
    __shared__ unsigned Bs[16][132];

    const int b = blockIdx.x;
    const float *A, *B, *bias;
    float* C;
    int bb;
    if (b < 32)       { bb = b;       A = q; B = Wq; bias = bq; C = Qp; }
    else if (b < 160) { bb = b - 32;  A = k; B = Wk; bias = bk; C = Kp; }
    else              { bb = b - 160; A = v; B = Wv; bias = bv; C = Vp; }
    const int m0 = (bb >> 2) * 128;
    const int n0 = (bb & 3) * 128;

    tgemm_block(A, B, C, DM, DM, DM, m0, n0, DM, 1.0f, bias, As, Bs);
}

// ---------------------------------------------------------------------------
// attnv tf32 (verified in R12): head-pair tiles + split-K.
// ---------------------------------------------------------------------------
__global__ __launch_bounds__(256) void attnv_tf32(
    const float* __restrict__ E, const float* __restrict__ V,
    float* __restrict__ Opart)
{
    __shared__ unsigned As0[16][132];
    __shared__ unsigned As1[16][132];
    __shared__ unsigned Bs[16][132];

    const int hp = blockIdx.y;
    const int m0 = blockIdx.x * 128;
    const int sp = blockIdx.z;
    const float* Eh0 = E + (long)(2 * hp)     * ((long)LQ * PK);
    const float* Eh1 = E + (long)(2 * hp + 1) * ((long)LQ * PK);

    const int t    = threadIdx.x;
    const int w    = t >> 5;
    const int lane = t & 31;
    const int grp  = lane >> 2;
    const int tid4 = lane & 3;
    const int wm = (w & 1) * 64;
    const int wn = (w >> 1) * 32;

    const int srow = t >> 1;
    const int sk   = (t & 1) * 8;
    const int bkr  = t >> 4;
    const int bnc  = (t & 15) * 8;

    float acc[4][4][4];
#pragma unroll
    for (int mi = 0; mi < 4; mi++)
#pragma unroll
        for (int nj = 0; nj < 4; nj++)
#pragma unroll
            for (int q = 0; q < 4; q++) acc[mi][nj][q] = 0.0f;

    const float* a0Ptr = Eh0 + (long)(m0 + srow) * PK + sp * CHUNK + sk;
    const float* a1Ptr = Eh1 + (long)(m0 + srow) * PK + sp * CHUNK + sk;
    const float* bPtr  = V + (long)(sp * CHUNK + bkr) * DM + hp * 128 + bnc;

    const unsigned (*Ap)[132] = (wn < 64) ? As0 : As1;
    const int wnl = wn;

    for (int k0 = 0; k0 < CHUNK; k0 += 16) {
        float4 p00 = *(const float4*)(a0Ptr + k0);
        float4 p01 = *(const float4*)(a0Ptr + k0 + 4);
        float4 p10 = *(const float4*)(a1Ptr + k0);
        float4 p11 = *(const float4*)(a1Ptr + k0 + 4);
        float4 bv0 = *(const float4*)(bPtr + (long)k0 * DM);
        float4 bv1 = *(const float4*)(bPtr + (long)k0 * DM + 4);
        As0[sk + 0][srow] = f2tf(p00.x); As0[sk + 1][srow] = f2tf(p00.y);
        As0[sk + 2][srow] = f2tf(p00.z); As0[sk + 3][srow] = f2tf(p00.w);
        As0[sk + 4][srow] = f2tf(p01.x); As0[sk + 5][srow] = f2tf(p01.y);
        As0[sk + 6][srow] = f2tf(p01.z); As0[sk + 7][srow] = f2tf(p01.w);
        As1[sk + 0][srow] = f2tf(p10.x); As1[sk + 1][srow] = f2tf(p10.y);
        As1[sk + 2][srow] = f2tf(p10.z); As1[sk + 3][srow] = f2tf(p10.w);
        As1[sk + 4][srow] = f2tf(p11.x); As1[sk + 5][srow] = f2tf(p11.y);
        As1[sk + 6][srow] = f2tf(p11.z); As1[sk + 7][srow] = f2tf(p11.w);
        Bs[bkr][bnc + 0] = f2tf(bv0.x); Bs[bkr][bnc + 1] = f2tf(bv0.y);
        Bs[bkr][bnc + 2] = f2tf(bv0.z); Bs[bkr][bnc + 3] = f2tf(bv0.w);
        Bs[bkr][bnc + 4] = f2tf(bv1.x); Bs[bkr][bnc + 5] = f2tf(bv1.y);
        Bs[bkr][bnc + 6] = f2tf(bv1.z); Bs[bkr][bnc + 7] = f2tf(bv1.w);
        __syncthreads();

#pragma unroll
        for (int ks = 0; ks < 16; ks += 8) {
            unsigned af[4][4];
#pragma unroll
            for (int mi = 0; mi < 4; mi++) {
                int mb = wm + mi * 16;
                af[mi][0] = Ap[ks + tid4][mb + grp];
                af[mi][1] = Ap[ks + tid4][mb + 8 + grp];
                af[mi][2] = Ap[ks + 4 + tid4][mb + grp];
                af[mi][3] = Ap[ks + 4 + tid4][mb + 8 + grp];
            }
#pragma unroll
            for (int nj = 0; nj < 4; nj++) {
                unsigned bf[2];
                bf[0] = Bs[ks + tid4][wnl + nj * 8 + grp];
                bf[1] = Bs[ks + 4 + tid4][wnl + nj * 8 + grp];
#pragma unroll
                for (int mi = 0; mi < 4; mi++)
                    mma_tf32(acc[mi][nj], af[mi], bf);
            }
        }
        __syncthreads();
    }

    float* Ob = Opart + (long)sp * ((long)LQ * DM);
#pragma unroll
    for (int mi = 0; mi < 4; mi++) {
        int r = m0 + wm + mi * 16 + grp;
#pragma unroll
        for (int nj = 0; nj < 4; nj++) {
            int c = hp * 128 + wnl + nj * 8 + 2 * tid4;
            *(float2*)&Ob[(long)r * DM + c] =
                make_float2(acc[mi][nj][0], acc[mi][nj][1]);
            *(float2*)&Ob[(long)(r + 8) * DM + c] =
                make_float2(acc[mi][nj][2], acc[mi][nj][3]);
        }
    }
}

// ---------------------------------------------------------------------------
// bias_exp_v4 (verified in R14): bias via mma; grid (LQ, PSPLIT).
// ---------------------------------------------------------------------------
extern __shared__ float db_buf[];  // 2 * TPB * NR floats = 51.2 KB

__global__ __launch_bounds__(256) void bias_exp_v4(
    const float* __restrict__ rbf, const float* __restrict__ Wr,
    const float* __restrict__ br, float* __restrict__ S,
    float* __restrict__ Zp)
{
    __shared__ float zpart[8][NH];

    const int l    = blockIdx.x;
    const int pc   = blockIdx.y;
    const int t    = threadIdx.x;
    const int w    = t >> 5;
    const int lane = t & 31;
    const int g    = lane >> 2;
    const int t4   = lane & 3;

    unsigned bfr[7][2];
#pragma unroll
    for (int ks = 0; ks < 7; ks++) {
        int k0 = ks * 8 + t4;
        int k1 = k0 + 4;
        float w0 = (k0 < NR) ? Wr[g * NR + k0] : 0.0f;
        float w1 = (k1 < NR) ? Wr[g * NR + k1] : 0.0f;
        bfr[ks][0] = f2tf(w0);
        bfr[ks][1] = f2tf(w1);
    }
    const float brh0 = br[2 * t4];
    const float brh1 = br[2 * t4 + 1];

    const float* rbf_base = rbf + (long)l * PK * NR + (long)pc * PCH * NR;
    float* buf0 = db_buf;
    float* buf1 = db_buf + TPB * NR;
    const int NOPS = TPB * NR / 4;  // 1600

    for (int i = t; i < NOPS; i += 256)
        cp16(buf0 + i * 4, rbf_base + (long)i * 4);
    cp_commit();

    float zacc0 = 0.f, zacc1 = 0.f;
    const long lp = (long)l * PK;
    const int NT = PCH / TPB;  // 4

    for (int tile = 0; tile < NT; tile++) {
        float* cur = (tile & 1) ? buf1 : buf0;
        float* nxt = (tile & 1) ? buf0 : buf1;

        cp_wait_all();
        __syncthreads();

        if (tile + 1 < NT) {
            const float* src = rbf_base + (long)(tile + 1) * TPB * NR;
            for (int i = t; i < NOPS; i += 256)
                cp16(nxt + i * 4, src + (long)i * 4);
            cp_commit();
        }

        const float* r0 = cur + (w * 16 + g) * NR;
        const float* r1 = r0 + 8 * NR;
        float acc[4] = {0.f, 0.f, 0.f, 0.f};
#pragma unroll
        for (int ks = 0; ks < 7; ks++) {
            int k0 = ks * 8 + t4;
            int k1 = k0 + 4;
            unsigned af[4];
            af[0] = (k0 < NR) ? __float_as_uint(r0[k0]) : 0u;
            af[1] = (k0 < NR) ? __float_as_uint(r1[k0]) : 0u;
            af[2] = (k1 < NR) ? __float_as_uint(r0[k1]) : 0u;
            af[3] = (k1 < NR) ? __float_as_uint(r1[k1]) : 0u;
            mma_tf32(acc, af, bfr[ks]);
        }

        const int p  = pc * PCH + tile * TPB + w * 16 + g;
        const int h0 = 2 * t4;
        float* s00 = S + (long)h0 * ((long)LQ * PK) + lp + p;
        float* s01 = s00 + (long)LQ * PK;
        float* s10 = s00 + 8;
        float* s11 = s01 + 8;

        float e00 = __expf(*s00 + acc[0] + brh0);
        float e01 = __expf(*s01 + acc[1] + brh1);
        float e10 = __expf(*s10 + acc[2] + brh0);
        float e11 = __expf(*s11 + acc[3] + brh1);
        *s00 = e00; *s01 = e01; *s10 = e10; *s11 = e11;
        zacc0 += e00 + e10;
        zacc1 += e01 + e11;
    }

#pragma unroll
    for (int o = 4; o <= 16; o <<= 1) {
        zacc0 += __shfl_xor_sync(0xFFFFFFFFu, zacc0, o);
        zacc1 += __shfl_xor_sync(0xFFFFFFFFu, zacc1, o);
    }
    if (lane < 4) {
        zpart[w][2 * t4]     = zacc0;
        zpart[w][2 * t4 + 1] = zacc1;
    }
    __syncthreads();
    if (t < NH) {
        float s = 0.f;
#pragma unroll
        for (int ww = 0; ww < 8; ww++) s += zpart[ww][t];
        Zp[((long)pc * LQ + l) * NH + t] = s;
    }
}

// ---------------------------------------------------------------------------
__global__ __launch_bounds__(256) void rz_finalize(
    const float* __restrict__ Zp, float* __restrict__ rZ)
{
    const int i = blockIdx.x * 256 + threadIdx.x;
    float s = 0.f;
#pragma unroll
    for (int c = 0; c < PSPLIT; c++) s += Zp[(long)c * LQ * NH + i];
    rZ[i] = 1.0f / s;
}

// ---------------------------------------------------------------------------
__global__ __launch_bounds__(256) void attnv_reduce(
    const float* __restrict__ Opart, const float* __restrict__ rZ,
    float* __restrict__ O)
{
    const int idx = blockIdx.x * 256 + threadIdx.x;
    const int l  = idx / (DM / 4);
    const int d4 = idx % (DM / 4);
    const int h  = d4 / (DH / 4);

    float4 s = make_float4(0.f, 0.f, 0.f, 0.f);
#pragma unroll
    for (int sp = 0; sp < SPLIT; sp++) {
        float4 v = *(const float4*)(Opart + (long)sp * ((long)LQ * DM) + (long)idx * 4);
        s.x += v.x; s.y += v.y; s.z += v.z; s.w += v.w;
    }
    const float sc = rZ[l * NH + h];
    s.x *= sc; s.y *= sc; s.z *= sc; s.w *= sc;
    *(float4*)(O + (long)idx * 4) = s;
}

// ---------------------------------------------------------------------------
__global__ __launch_bounds__(256) void attn_mean_kernel(
    const float* __restrict__ E, const float* __restrict__ rZ,
    float* __restrict__ out)
{
    __shared__ float rz[NH];
    const int l = blockIdx.x >> 4;
    const int p = ((blockIdx.x & 15) << 8) + threadIdx.x;
    if (threadIdx.x < NH) rz[threadIdx.x] = rZ[l * NH + threadIdx.x];
    __syncthreads();

    const float* El = E + (long)l * PK + p;
    float s = 0.0f;
#pragma unroll
    for (int h = 0; h < NH; h++)
        s = fmaf(El[(long)h * ((long)LQ * PK)], rz[h], s);
    out[(long)l * PK + p] = s * 0.125f;
}

// ---------------------------------------------------------------------------
__global__ __launch_bounds__(256) void ln_kernel(
    const float* __restrict__ query, const float* __restrict__ Xo,
    const float* __restrict__ gamma, const float* __restrict__ beta,
    float* __restrict__ y)
{
    __shared__ float rs[8], rq[8];
    const int l = blockIdx.x;
    const int t = threadIdx.x;
    const int lane = t & 31, warp = t >> 5;

    float2 q  = *(const float2*)(query + (long)l * DM + t * 2);
    float2 xo = *(const float2*)(Xo    + (long)l * DM + t * 2);
    float x0 = q.x + xo.x;
    float x1 = q.y + xo.y;

    float s  = x0 + x1;
    float sq = x0 * x0 + x1 * x1;
#pragma unroll
    for (int o = 16; o > 0; o >>= 1) {
        s  += __shfl_xor_sync(0xFFFFFFFFu, s, o);
        sq += __shfl_xor_sync(0xFFFFFFFFu, sq, o);
    }
    if (lane == 0) { rs[warp] = s; rq[warp] = sq; }
    __syncthreads();
    if (warp == 0) {
        float a = (lane < 8) ? rs[lane] : 0.0f;
        float b = (lane < 8) ? rq[lane] : 0.0f;
#pragma unroll
        for (int o = 4; o > 0; o >>= 1) {
            a += __shfl_xor_sync(0xFFFFFFFFu, a, o);
            b += __shfl_xor_sync(0xFFFFFFFFu, b, o);
        }
        if (lane == 0) { rs[0] = a; rq[0] = b; }
    }
    __syncthreads();

    const float mean = rs[0] * (1.0f / DM);
    const float var  = rq[0] * (1.0f / DM) - mean * mean;
    const float rstd = rsqrtf(var + 1e-5f);

    float2 g = *(const float2*)(gamma + t * 2);
    float2 b = *(const float2*)(beta + t * 2);
    float2 o;
    o.x = (x0 - mean) * rstd * g.x + b.x;
    o.y = (x1 - mean) * rstd * g.y + b.y;
    *(float2*)(y + (long)l * DM + t * 2) = o;
}

// ---------------------------------------------------------------------------
extern "C" void kernel_launch(void* const* d_in, const int* in_sizes, int n_in,
                              void* d_out, int out_size)
{
    const float* query = (const float*)d_in[0];
    const float* key   = (const float*)d_in[1];
    const float* value = (const float*)d_in[2];
    const float* rbf   = (const float*)d_in[3];
    const float* Wq = (const float*)d_in[4];
    const float* bq = (const float*)d_in[5];
    const float* Wk = (const float*)d_in[6];
    const float* bk = (const float*)d_in[7];
    const float* Wv = (const float*)d_in[8];
    const float* bv = (const float*)d_in[9];
    const float* Wr = (const float*)d_in[10];
    const float* br = (const float*)d_in[11];
    const float* Wo = (const float*)d_in[12];
    const float* bo = (const float*)d_in[13];
    const float* gamma = (const float*)d_in[14];
    const float* beta  = (const float*)d_in[15];
    float* out = (float*)d_out;

    float *Qp, *Kp, *Vp, *S, *Zp, *rZ, *O, *Op, *Xo;
    cudaGetSymbolAddress((void**)&Qp, g_Qp);
    cudaGetSymbolAddress((void**)&Kp, g_Kp);
    cudaGetSymbolAddress((void**)&Vp, g_Vp);
    cudaGetSymbolAddress((void**)&S,  g_S);
    cudaGetSymbolAddress((void**)&Zp, g_Zp);
    cudaGetSymbolAddress((void**)&rZ, g_rZ);
    cudaGetSymbolAddress((void**)&O,  g_O);
    cudaGetSymbolAddress((void**)&Op, g_Op);
    cudaGetSymbolAddress((void**)&Xo, g_Xo);

    const int dynsmem = 2 * TPB * NR * sizeof(float);
    cudaFuncSetAttribute(bias_exp_v4, cudaFuncAttributeMaxDynamicSharedMemorySize,
                         dynsmem);

    // QKV projections in ONE launch (288 equal blocks, ~2 full waves)
    qkv_fused<<<288, 256>>>(query, key, value, Wq, Wk, Wv, bq, bk, bv,
                            Qp, Kp, Vp);

    // Scores: per head, S[h][l][p] = 0.125 * Q_h[l,:] . K_h[p,:]  (K=64)
    tgemm_nt<<<dim3(PK / 128, LQ / 128, NH), 256>>>(Qp, DM, DH, Kp, DM, DH,
                                                    S, PK, (long)LQ * PK,
                                                    DH, 0.125f, nullptr);

    // bias from cross_rbf (tensor-core) + exp + per-(l,h,chunk) Z partials
    bias_exp_v4<<<dim3(LQ, PSPLIT), 256, dynsmem>>>(rbf, Wr, br, S, Zp);
    rz_finalize<<<(LQ * NH) / 256, 256>>>(Zp, rZ);

    // attn @ V (tf32, head pairs, split-K), then reduce + 1/Z
    attnv_tf32<<<dim3(LQ / 128, NH / 2, SPLIT), 256>>>(S, Vp, Op);
    attnv_reduce<<<(LQ * DM / 4) / 256, 256>>>(Op, rZ, O);

    // attn.mean over heads -> second output
    attn_mean_kernel<<<LQ * (PK / 256), 256>>>(S, rZ, out + (long)LQ * DM);

    // output projection (tf32)
    tgemm_nt<<<dim3(DM / 128, LQ / 128, 1), 256>>>(O, DM, 0, Wo, DM, 0,
                                                   Xo, DM, 0, DM, 1.0f, bo);

    // residual + layernorm -> first output
    ln_kernel<<<LQ, 256>>>(query, Xo, gamma, beta, out);
}

// round 17
// speedup vs baseline: 2.8952x; 1.1513x over previous
#include <cuda_runtime.h>
#include <cuda_fp16.h>
#include <cstdint>
#include <math.h>

#define LQ 1024
#define PK 4096
#define DM 512
#define NH 8
#define DH 64
#define NR 50
#define TPB 128            // p-tile for bias_exp
#define PSPLIT 8           // p-chunk split for bias_exp
#define PCH (PK / PSPLIT)  // 512
#define SPLIT 8            // split-K factor for attnv
#define CHUNK (PK / SPLIT) // 512

// ---------------- scratch (device globals; no allocations allowed) ----------
__device__ float  g_Qp[LQ * DM];            // 2 MB
__device__ float  g_Kp[PK * DM];            // 8 MB
__device__ float  g_Vp[PK * DM];            // 8 MB
__device__ float  g_S[NH * LQ * PK];        // 134 MB  logits, [H][L][P]
__device__ __half g_E[NH * LQ * PK];        // 67 MB   exp(logits), fp16
__device__ float  g_Zp[PSPLIT * LQ * NH];   // Z partials per p-chunk
__device__ float  g_rZ[LQ * NH];            // 1/Z per (l,h)
__device__ float  g_O[LQ * DM];             // attention output (pre out-proj)
__device__ float  g_Op[SPLIT * LQ * DM];    // 16 MB   split-K partials
__device__ float  g_Xo[LQ * DM];            // out-proj result

// ---------------- cp.async helpers ----------------
__device__ __forceinline__ void cp16(void* smem_dst, const void* gmem_src) {
    unsigned s = (unsigned)__cvta_generic_to_shared(smem_dst);
    asm volatile("cp.async.cg.shared.global [%0], [%1], 16;" :: "r"(s), "l"(gmem_src));
}
__device__ __forceinline__ void cp_commit() {
    asm volatile("cp.async.commit_group;" ::: "memory");
}
__device__ __forceinline__ void cp_wait_all() {
    asm volatile("cp.async.wait_group 0;" ::: "memory");
}

// ---------------- tf32 mma helpers ----------------
__device__ __forceinline__ unsigned f2tf(float x) {
    unsigned r;
    asm("cvt.rna.tf32.f32 %0, %1;" : "=r"(r) : "f"(x));
    return r;
}
__device__ __forceinline__ void mma_tf32(float* d, const unsigned* a,
                                         const unsigned* b) {
    asm volatile(
        "mma.sync.aligned.m16n8k8.row.col.f32.tf32.tf32.f32 "
        "{%0,%1,%2,%3}, {%4,%5,%6,%7}, {%8,%9}, {%0,%1,%2,%3};\n"
        : "+f"(d[0]), "+f"(d[1]), "+f"(d[2]), "+f"(d[3])
        : "r"(a[0]), "r"(a[1]), "r"(a[2]), "r"(a[3]),
          "r"(b[0]), "r"(b[1]));
}

// ---------------------------------------------------------------------------
// Shared tf32 GEMM block body. Smem stride 136 -> fragment-load bank pattern
// 8*tid4 + grp covers all 32 banks (conflict-free; 132 was 2-way).
// ---------------------------------------------------------------------------
__device__ __forceinline__ void tgemm_block(
    const float* __restrict__ A, const float* __restrict__ B,
    float* __restrict__ C, int lda, int ldb, int ldc,
    int m0, int n0, int K, float alpha, const float* __restrict__ bias,
    unsigned (*As)[136], unsigned (*Bs)[136])
{
    const int t    = threadIdx.x;
    const int w    = t >> 5;
    const int lane = t & 31;
    const int grp  = lane >> 2;
    const int tid4 = lane & 3;
    const int wm = (w & 1) * 64;
    const int wn = (w >> 1) * 32;

    const int srow = t >> 1;
    const int sk   = (t & 1) * 8;

    float acc[4][4][4];
#pragma unroll
    for (int mi = 0; mi < 4; mi++)
#pragma unroll
        for (int nj = 0; nj < 4; nj++)
#pragma unroll
            for (int q = 0; q < 4; q++) acc[mi][nj][q] = 0.0f;

    const float* aPtr = A + (long)(m0 + srow) * lda + sk;
    const float* bPtr = B + (long)(n0 + srow) * ldb + sk;

    for (int k0 = 0; k0 < K; k0 += 16) {
        float4 a0v = *(const float4*)(aPtr + k0);
        float4 a1v = *(const float4*)(aPtr + k0 + 4);
        float4 b0v = *(const float4*)(bPtr + k0);
        float4 b1v = *(const float4*)(bPtr + k0 + 4);
        As[sk + 0][srow] = f2tf(a0v.x); As[sk + 1][srow] = f2tf(a0v.y);
        As[sk + 2][srow] = f2tf(a0v.z); As[sk + 3][srow] = f2tf(a0v.w);
        As[sk + 4][srow] = f2tf(a1v.x); As[sk + 5][srow] = f2tf(a1v.y);
        As[sk + 6][srow] = f2tf(a1v.z); As[sk + 7][srow] = f2tf(a1v.w);
        Bs[sk + 0][srow] = f2tf(b0v.x); Bs[sk + 1][srow] = f2tf(b0v.y);
        Bs[sk + 2][srow] = f2tf(b0v.z); Bs[sk + 3][srow] = f2tf(b0v.w);
        Bs[sk + 4][srow] = f2tf(b1v.x); Bs[sk + 5][srow] = f2tf(b1v.y);
        Bs[sk + 6][srow] = f2tf(b1v.z); Bs[sk + 7][srow] = f2tf(b1v.w);
        __syncthreads();

#pragma unroll
        for (int ks = 0; ks < 16; ks += 8) {
            unsigned af[4][4];
#pragma unroll
            for (int mi = 0; mi < 4; mi++) {
                int mb = wm + mi * 16;
                af[mi][0] = As[ks + tid4][mb + grp];
                af[mi][1] = As[ks + tid4][mb + 8 + grp];
                af[mi][2] = As[ks + 4 + tid4][mb + grp];
                af[mi][3] = As[ks + 4 + tid4][mb + 8 + grp];
            }
#pragma unroll
            for (int nj = 0; nj < 4; nj++) {
                unsigned bf[2];
                bf[0] = Bs[ks + tid4][wn + nj * 8 + grp];
                bf[1] = Bs[ks + 4 + tid4][wn + nj * 8 + grp];
#pragma unroll
                for (int mi = 0; mi < 4; mi++)
                    mma_tf32(acc[mi][nj], af[mi], bf);
            }
        }
        __syncthreads();
    }

#pragma unroll
    for (int mi = 0; mi < 4; mi++) {
        int r = m0 + wm + mi * 16 + grp;
#pragma unroll
        for (int nj = 0; nj < 4; nj++) {
            int c = n0 + wn + nj * 8 + 2 * tid4;
            float bb0 = 0.f, bb1 = 0.f;
            if (bias) { bb0 = bias[c]; bb1 = bias[c + 1]; }
            float2 v0 = make_float2(fmaf(alpha, acc[mi][nj][0], bb0),
                                    fmaf(alpha, acc[mi][nj][1], bb1));
            float2 v1 = make_float2(fmaf(alpha, acc[mi][nj][2], bb0),
                                    fmaf(alpha, acc[mi][nj][3], bb1));
            *(float2*)&C[(long)r * ldc + c]       = v0;
            *(float2*)&C[(long)(r + 8) * ldc + c] = v1;
        }
    }
}

// ---------------------------------------------------------------------------
__global__ __launch_bounds__(256) void tgemm_nt(
    const float* __restrict__ A, int lda, int aStride,
    const float* __restrict__ B, int ldb, int bStride,
    float* __restrict__ C, int ldc, long cStride,
    int K, float alpha, const float* __restrict__ bias)
{
    __shared__ unsigned As[16][136];
    __shared__ unsigned Bs[16][136];
    const int bz = blockIdx.z;
    tgemm_block(A + (long)bz * aStride, B + (long)bz * bStride,
                C + (long)bz * cStride, lda, ldb, ldc,
                blockIdx.y * 128, blockIdx.x * 128, K, alpha, bias, As, Bs);
}

// ---------------------------------------------------------------------------
// qkv_fused (verified in R16): ONE launch, 288 equal-work blocks.
// ---------------------------------------------------------------------------
__global__ __launch_bounds__(256) void qkv_fused(
    const float* __restrict__ q, const float* __restrict__ k,
    const float* __restrict__ v,
    const float* __restrict__ Wq, const float* __restrict__ Wk,
    const float* __restrict__ Wv,
    const float* __restrict__ bq, const float* __restrict__ bk,
    const float* __restrict__ bv,
    float* __restrict__ Qp, float* __restrict__ Kp, float* __restrict__ Vp)
{
    __shared__ unsigned As[16][136];
    __shared__ unsigned Bs[16][136];

    const int b = blockIdx.x;
    const float *A, *B, *bias;
    float* C;
    int bb;
    if (b < 32)       { bb = b;       A = q; B = Wq; bias = bq; C = Qp; }
    else if (b < 160) { bb = b - 32;  A = k; B = Wk; bias = bk; C = Kp; }
    else              { bb = b - 160; A = v; B = Wv; bias = bv; C = Vp; }
    const int m0 = (bb >> 2) * 128;
    const int n0 = (bb & 3) * 128;

    tgemm_block(A, B, C, DM, DM, DM, m0, n0, DM, 1.0f, bias, As, Bs);
}

// ---------------------------------------------------------------------------
// attnv tf32 over fp16 E: head-pair tiles + split-K. A operand (E) loaded as
// 8 halfs per uint4, converted to tf32 in staging; mma core unchanged.
// ---------------------------------------------------------------------------
__global__ __launch_bounds__(256) void attnv_tf32(
    const __half* __restrict__ E, const float* __restrict__ V,
    float* __restrict__ Opart)
{
    __shared__ unsigned As0[16][136];
    __shared__ unsigned As1[16][136];
    __shared__ unsigned Bs[16][136];

    const int hp = blockIdx.y;
    const int m0 = blockIdx.x * 128;
    const int sp = blockIdx.z;
    const __half* Eh0 = E + (long)(2 * hp)     * ((long)LQ * PK);
    const __half* Eh1 = E + (long)(2 * hp + 1) * ((long)LQ * PK);

    const int t    = threadIdx.x;
    const int w    = t >> 5;
    const int lane = t & 31;
    const int grp  = lane >> 2;
    const int tid4 = lane & 3;
    const int wm = (w & 1) * 64;
    const int wn = (w >> 1) * 32;

    const int srow = t >> 1;
    const int sk   = (t & 1) * 8;
    const int bkr  = t >> 4;
    const int bnc  = (t & 15) * 8;

    float acc[4][4][4];
#pragma unroll
    for (int mi = 0; mi < 4; mi++)
#pragma unroll
        for (int nj = 0; nj < 4; nj++)
#pragma unroll
            for (int q = 0; q < 4; q++) acc[mi][nj][q] = 0.0f;

    const __half* a0Ptr = Eh0 + (long)(m0 + srow) * PK + sp * CHUNK + sk;
    const __half* a1Ptr = Eh1 + (long)(m0 + srow) * PK + sp * CHUNK + sk;
    const float*  bPtr  = V + (long)(sp * CHUNK + bkr) * DM + hp * 128 + bnc;

    const unsigned (*Ap)[136] = (wn < 64) ? As0 : As1;
    const int wnl = wn;

    for (int k0 = 0; k0 < CHUNK; k0 += 16) {
        uint4 ra0 = *(const uint4*)(a0Ptr + k0);   // 8 halfs, 16B aligned
        uint4 ra1 = *(const uint4*)(a1Ptr + k0);
        float4 bv0 = *(const float4*)(bPtr + (long)k0 * DM);
        float4 bv1 = *(const float4*)(bPtr + (long)k0 * DM + 4);

        const __half2* h0 = (const __half2*)&ra0;
        const __half2* h1 = (const __half2*)&ra1;
        float2 f;
        f = __half22float2(h0[0]); As0[sk + 0][srow] = f2tf(f.x); As0[sk + 1][srow] = f2tf(f.y);
        f = __half22float2(h0[1]); As0[sk + 2][srow] = f2tf(f.x); As0[sk + 3][srow] = f2tf(f.y);
        f = __half22float2(h0[2]); As0[sk + 4][srow] = f2tf(f.x); As0[sk + 5][srow] = f2tf(f.y);
        f = __half22float2(h0[3]); As0[sk + 6][srow] = f2tf(f.x); As0[sk + 7][srow] = f2tf(f.y);
        f = __half22float2(h1[0]); As1[sk + 0][srow] = f2tf(f.x); As1[sk + 1][srow] = f2tf(f.y);
        f = __half22float2(h1[1]); As1[sk + 2][srow] = f2tf(f.x); As1[sk + 3][srow] = f2tf(f.y);
        f = __half22float2(h1[2]); As1[sk + 4][srow] = f2tf(f.x); As1[sk + 5][srow] = f2tf(f.y);
        f = __half22float2(h1[3]); As1[sk + 6][srow] = f2tf(f.x); As1[sk + 7][srow] = f2tf(f.y);

        Bs[bkr][bnc + 0] = f2tf(bv0.x); Bs[bkr][bnc + 1] = f2tf(bv0.y);
        Bs[bkr][bnc + 2] = f2tf(bv0.z); Bs[bkr][bnc + 3] = f2tf(bv0.w);
        Bs[bkr][bnc + 4] = f2tf(bv1.x); Bs[bkr][bnc + 5] = f2tf(bv1.y);
        Bs[bkr][bnc + 6] = f2tf(bv1.z); Bs[bkr][bnc + 7] = f2tf(bv1.w);
        __syncthreads();

#pragma unroll
        for (int ks = 0; ks < 16; ks += 8) {
            unsigned af[4][4];
#pragma unroll
            for (int mi = 0; mi < 4; mi++) {
                int mb = wm + mi * 16;
                af[mi][0] = Ap[ks + tid4][mb + grp];
                af[mi][1] = Ap[ks + tid4][mb + 8 + grp];
                af[mi][2] = Ap[ks + 4 + tid4][mb + grp];
                af[mi][3] = Ap[ks + 4 + tid4][mb + 8 + grp];
            }
#pragma unroll
            for (int nj = 0; nj < 4; nj++) {
                unsigned bf[2];
                bf[0] = Bs[ks + tid4][wnl + nj * 8 + grp];
                bf[1] = Bs[ks + 4 + tid4][wnl + nj * 8 + grp];
#pragma unroll
                for (int mi = 0; mi < 4; mi++)
                    mma_tf32(acc[mi][nj], af[mi], bf);
            }
        }
        __syncthreads();
    }

    float* Ob = Opart + (long)sp * ((long)LQ * DM);
#pragma unroll
    for (int mi = 0; mi < 4; mi++) {
        int r = m0 + wm + mi * 16 + grp;
#pragma unroll
        for (int nj = 0; nj < 4; nj++) {
            int c = hp * 128 + wnl + nj * 8 + 2 * tid4;
            *(float2*)&Ob[(long)r * DM + c] =
                make_float2(acc[mi][nj][0], acc[mi][nj][1]);
            *(float2*)&Ob[(long)(r + 8) * DM + c] =
                make_float2(acc[mi][nj][2], acc[mi][nj][3]);
        }
    }
}

// ---------------------------------------------------------------------------
// bias_exp_v5: bias via mma (verified R14 core); reads fp32 logits S, writes
// fp16 E (S is never written -> 134 MB less traffic). grid (LQ, PSPLIT).
// ---------------------------------------------------------------------------
extern __shared__ float db_buf[];  // 2 * TPB * NR floats = 51.2 KB

__global__ __launch_bounds__(256) void bias_exp_v5(
    const float* __restrict__ rbf, const float* __restrict__ Wr,
    const float* __restrict__ br, const float* __restrict__ S,
    __half* __restrict__ E, float* __restrict__ Zp)
{
    __shared__ float zpart[8][NH];

    const int l    = blockIdx.x;
    const int pc   = blockIdx.y;
    const int t    = threadIdx.x;
    const int w    = t >> 5;
    const int lane = t & 31;
    const int g    = lane >> 2;
    const int t4   = lane & 3;

    unsigned bfr[7][2];
#pragma unroll
    for (int ks = 0; ks < 7; ks++) {
        int k0 = ks * 8 + t4;
        int k1 = k0 + 4;
        float w0 = (k0 < NR) ? Wr[g * NR + k0] : 0.0f;
        float w1 = (k1 < NR) ? Wr[g * NR + k1] : 0.0f;
        bfr[ks][0] = f2tf(w0);
        bfr[ks][1] = f2tf(w1);
    }
    const float brh0 = br[2 * t4];
    const float brh1 = br[2 * t4 + 1];

    const float* rbf_base = rbf + (long)l * PK * NR + (long)pc * PCH * NR;
    float* buf0 = db_buf;
    float* buf1 = db_buf + TPB * NR;
    const int NOPS = TPB * NR / 4;  // 1600

    for (int i = t; i < NOPS; i += 256)
        cp16(buf0 + i * 4, rbf_base + (long)i * 4);
    cp_commit();

    float zacc0 = 0.f, zacc1 = 0.f;
    const long lp = (long)l * PK;
    const int NT = PCH / TPB;  // 4

    for (int tile = 0; tile < NT; tile++) {
        float* cur = (tile & 1) ? buf1 : buf0;
        float* nxt = (tile & 1) ? buf0 : buf1;

        cp_wait_all();
        __syncthreads();

        if (tile + 1 < NT) {
            const float* src = rbf_base + (long)(tile + 1) * TPB * NR;
            for (int i = t; i < NOPS; i += 256)
                cp16(nxt + i * 4, src + (long)i * 4);
            cp_commit();
        }

        const float* r0 = cur + (w * 16 + g) * NR;
        const float* r1 = r0 + 8 * NR;
        float acc[4] = {0.f, 0.f, 0.f, 0.f};
#pragma unroll
        for (int ks = 0; ks < 7; ks++) {
            int k0 = ks * 8 + t4;
            int k1 = k0 + 4;
            unsigned af[4];
            af[0] = (k0 < NR) ? __float_as_uint(r0[k0]) : 0u;
            af[1] = (k0 < NR) ? __float_as_uint(r1[k0]) : 0u;
            af[2] = (k1 < NR) ? __float_as_uint(r0[k1]) : 0u;
            af[3] = (k1 < NR) ? __float_as_uint(r1[k1]) : 0u;
            mma_tf32(acc, af, bfr[ks]);
        }

        const int p  = pc * PCH + tile * TPB + w * 16 + g;
        const int h0 = 2 * t4;
        const float* s00 = S + (long)h0 * ((long)LQ * PK) + lp + p;
        const float* s01 = s00 + (long)LQ * PK;
        __half* e00 = E + (long)h0 * ((long)LQ * PK) + lp + p;
        __half* e01 = e00 + (long)LQ * PK;

        float v00 = __expf(s00[0] + acc[0] + brh0);
        float v01 = __expf(s01[0] + acc[1] + brh1);
        float v10 = __expf(s00[8] + acc[2] + brh0);
        float v11 = __expf(s01[8] + acc[3] + brh1);
        e00[0] = __float2half(v00);
        e01[0] = __float2half(v01);
        e00[8] = __float2half(v10);
        e01[8] = __float2half(v11);
        zacc0 += v00 + v10;
        zacc1 += v01 + v11;
    }

#pragma unroll
    for (int o = 4; o <= 16; o <<= 1) {
        zacc0 += __shfl_xor_sync(0xFFFFFFFFu, zacc0, o);
        zacc1 += __shfl_xor_sync(0xFFFFFFFFu, zacc1, o);
    }
    if (lane < 4) {
        zpart[w][2 * t4]     = zacc0;
        zpart[w][2 * t4 + 1] = zacc1;
    }
    __syncthreads();
    if (t < NH) {
        float s = 0.f;
#pragma unroll
        for (int ww = 0; ww < 8; ww++) s += zpart[ww][t];
        Zp[((long)pc * LQ + l) * NH + t] = s;
    }
}

// ---------------------------------------------------------------------------
__global__ __launch_bounds__(256) void rz_finalize(
    const float* __restrict__ Zp, float* __restrict__ rZ)
{
    const int i = blockIdx.x * 256 + threadIdx.x;
    float s = 0.f;
#pragma unroll
    for (int c = 0; c < PSPLIT; c++) s += Zp[(long)c * LQ * NH + i];
    rZ[i] = 1.0f / s;
}

// ---------------------------------------------------------------------------
__global__ __launch_bounds__(256) void attnv_reduce(
    const float* __restrict__ Opart, const float* __restrict__ rZ,
    float* __restrict__ O)
{
    const int idx = blockIdx.x * 256 + threadIdx.x;
    const int l  = idx / (DM / 4);
    const int d4 = idx % (DM / 4);
    const int h  = d4 / (DH / 4);

    float4 s = make_float4(0.f, 0.f, 0.f, 0.f);
#pragma unroll
    for (int sp = 0; sp < SPLIT; sp++) {
        float4 v = *(const float4*)(Opart + (long)sp * ((long)LQ * DM) + (long)idx * 4);
        s.x += v.x; s.y += v.y; s.z += v.z; s.w += v.w;
    }
    const float sc = rZ[l * NH + h];
    s.x *= sc; s.y *= sc; s.z *= sc; s.w *= sc;
    *(float4*)(O + (long)idx * 4) = s;
}

// ---------------------------------------------------------------------------
__global__ __launch_bounds__(256) void attn_mean_kernel(
    const __half* __restrict__ E, const float* __restrict__ rZ,
    float* __restrict__ out)
{
    __shared__ float rz[NH];
    const int l = blockIdx.x >> 4;
    const int p = ((blockIdx.x & 15) << 8) + threadIdx.x;
    if (threadIdx.x < NH) rz[threadIdx.x] = rZ[l * NH + threadIdx.x];
    __syncthreads();

    const __half* El = E + (long)l * PK + p;
    float s = 0.0f;
#pragma unroll
    for (int h = 0; h < NH; h++)
        s = fmaf(__half2float(El[(long)h * ((long)LQ * PK)]), rz[h], s);
    out[(long)l * PK + p] = s * 0.125f;
}

// ---------------------------------------------------------------------------
__global__ __launch_bounds__(256) void ln_kernel(
    const float* __restrict__ query, const float* __restrict__ Xo,
    const float* __restrict__ gamma, const float* __restrict__ beta,
    float* __restrict__ y)
{
    __shared__ float rs[8], rq[8];
    const int l = blockIdx.x;
    const int t = threadIdx.x;
    const int lane = t & 31, warp = t >> 5;

    float2 q  = *(const float2*)(query + (long)l * DM + t * 2);
    float2 xo = *(const float2*)(Xo    + (long)l * DM + t * 2);
    float x0 = q.x + xo.x;
    float x1 = q.y + xo.y;

    float s  = x0 + x1;
    float sq = x0 * x0 + x1 * x1;
#pragma unroll
    for (int o = 16; o > 0; o >>= 1) {
        s  += __shfl_xor_sync(0xFFFFFFFFu, s, o);
        sq += __shfl_xor_sync(0xFFFFFFFFu, sq, o);
    }
    if (lane == 0) { rs[warp] = s; rq[warp] = sq; }
    __syncthreads();
    if (warp == 0) {
        float a = (lane < 8) ? rs[lane] : 0.0f;
        float b = (lane < 8) ? rq[lane] : 0.0f;
#pragma unroll
        for (int o = 4; o > 0; o >>= 1) {
            a += __shfl_xor_sync(0xFFFFFFFFu, a, o);
            b += __shfl_xor_sync(0xFFFFFFFFu, b, o);
        }
        if (lane == 0) { rs[0] = a; rq[0] = b; }
    }
    __syncthreads();

    const float mean = rs[0] * (1.0f / DM);
    const float var  = rq[0] * (1.0f / DM) - mean * mean;
    const float rstd = rsqrtf(var + 1e-5f);

    float2 g = *(const float2*)(gamma + t * 2);
    float2 b = *(const float2*)(beta + t * 2);
    float2 o;
    o.x = (x0 - mean) * rstd * g.x + b.x;
    o.y = (x1 - mean) * rstd * g.y + b.y;
    *(float2*)(y + (long)l * DM + t * 2) = o;
}

// ---------------------------------------------------------------------------
extern "C" void kernel_launch(void* const* d_in, const int* in_sizes, int n_in,
                              void* d_out, int out_size)
{
    const float* query = (const float*)d_in[0];
    const float* key   = (const float*)d_in[1];
    const float* value = (const float*)d_in[2];
    const float* rbf   = (const float*)d_in[3];
    const float* Wq = (const float*)d_in[4];
    const float* bq = (const float*)d_in[5];
    const float* Wk = (const float*)d_in[6];
    const float* bk = (const float*)d_in[7];
    const float* Wv = (const float*)d_in[8];
    const float* bv = (const float*)d_in[9];
    const float* Wr = (const float*)d_in[10];
    const float* br = (const float*)d_in[11];
    const float* Wo = (const float*)d_in[12];
    const float* bo = (const float*)d_in[13];
    const float* gamma = (const float*)d_in[14];
    const float* beta  = (const float*)d_in[15];
    float* out = (float*)d_out;

    float *Qp, *Kp, *Vp, *S, *Zp, *rZ, *O, *Op, *Xo;
    __half* E;
    cudaGetSymbolAddress((void**)&Qp, g_Qp);
    cudaGetSymbolAddress((void**)&Kp, g_Kp);
    cudaGetSymbolAddress((void**)&Vp, g_Vp);
    cudaGetSymbolAddress((void**)&S,  g_S);
    cudaGetSymbolAddress((void**)&E,  g_E);
    cudaGetSymbolAddress((void**)&Zp, g_Zp);
    cudaGetSymbolAddress((void**)&rZ, g_rZ);
    cudaGetSymbolAddress((void**)&O,  g_O);
    cudaGetSymbolAddress((void**)&Op, g_Op);
    cudaGetSymbolAddress((void**)&Xo, g_Xo);

    const int dynsmem = 2 * TPB * NR * sizeof(float);
    cudaFuncSetAttribute(bias_exp_v5, cudaFuncAttributeMaxDynamicSharedMemorySize,
                         dynsmem);

    // QKV projections in ONE launch (288 equal blocks, ~2 full waves)
    qkv_fused<<<288, 256>>>(query, key, value, Wq, Wk, Wv, bq, bk, bv,
                            Qp, Kp, Vp);

    // Scores: per head, S[h][l][p] = 0.125 * Q_h[l,:] . K_h[p,:]  (K=64)
    tgemm_nt<<<dim3(PK / 128, LQ / 128, NH), 256>>>(Qp, DM, DH, Kp, DM, DH,
                                                    S, PK, (long)LQ * PK,
                                                    DH, 0.125f, nullptr);

    // bias from cross_rbf (tensor-core) + exp -> fp16 E + Z partials
    bias_exp_v5<<<dim3(LQ, PSPLIT), 256, dynsmem>>>(rbf, Wr, br, S, E, Zp);
    rz_finalize<<<(LQ * NH) / 256, 256>>>(Zp, rZ);

    // attn @ V (tf32 over fp16 E, head pairs, split-K), then reduce + 1/Z
    attnv_tf32<<<dim3(LQ / 128, NH / 2, SPLIT), 256>>>(E, Vp, Op);
    attnv_reduce<<<(LQ * DM / 4) / 256, 256>>>(Op, rZ, O);

    // attn.mean over heads -> second output
    attn_mean_kernel<<<LQ * (PK / 256), 256>>>(E, rZ, out + (long)LQ * DM);

    // output projection (tf32)
    tgemm_nt<<<dim3(DM / 128, LQ / 128, 1), 256>>>(O, DM, 0, Wo, DM, 0,
                                                   Xo, DM, 0, DM, 1.0f, bo);

    // residual + layernorm -> first output
    ln_kernel<<<LQ, 256>>>(query, Xo, gamma, beta, out);
}